// round 12
// baseline (speedup 1.0000x reference)
#include <cuda_runtime.h>
#include <cstdint>

// ---------------------------------------------------------------------------
// MultiHeadAttn: B=2, S=2048, D=1024, H=16, depth=64
// Stage 0: single merged round_tf32 pre-pass (q,k,v + 4 weights).
// Stage 1: merged QKV projections, cvt-free 3-stage pipeline mainloop.
// Stage 2: flash attention (unchanged R11): 64q CTA, 4 warps, 2 CTA/SM,
//          plain-tf32 QK and PV, cvt-free loops.
// Stage 3: fc output projection, 3-stage pipeline.
// ---------------------------------------------------------------------------

#define NEG_INF (-3.402823466e38f)

static constexpr int Bb = 2;
static constexpr int Ss = 2048;
static constexpr int Dd = 1024;
static constexpr int Hh = 16;
static constexpr int DP = 64;
static constexpr int MM = Bb * Ss;  // 4096

__device__ float g_Qp[(size_t)MM * Dd];
__device__ float g_Kh[(size_t)MM * Dd];
__device__ float g_VT[(size_t)MM * Dd];   // [B, H, DP, Ss]
__device__ float g_attn_scratch[(size_t)MM * Dd];
__device__ float g_FCin[(size_t)MM * Dd];
__device__ float g_qr[(size_t)MM * Dd];
__device__ float g_kr[(size_t)MM * Dd];
__device__ float g_vr[(size_t)MM * Dd];
__device__ float g_wqr[(size_t)Dd * Dd];
__device__ float g_wkr[(size_t)Dd * Dd];
__device__ float g_wvr[(size_t)Dd * Dd];
__device__ float g_wfr[(size_t)Dd * Dd];

// ---------------------------------------------------------------------------
// PTX helpers
// ---------------------------------------------------------------------------
__device__ __forceinline__ uint32_t cvta_smem(const void* p) {
    return (uint32_t)__cvta_generic_to_shared(p);
}
__device__ __forceinline__ void cp_async16(uint32_t dst, const void* src) {
    asm volatile("cp.async.cg.shared.global [%0], [%1], 16;\n" :: "r"(dst), "l"(src));
}
__device__ __forceinline__ void cp_commit() {
    asm volatile("cp.async.commit_group;\n");
}
__device__ __forceinline__ void cp_wait0() {
    asm volatile("cp.async.wait_group 0;\n");
}
__device__ __forceinline__ void cp_wait1() {
    asm volatile("cp.async.wait_group 1;\n");
}
__device__ __forceinline__ void ldsm_x4(uint32_t& r0, uint32_t& r1, uint32_t& r2, uint32_t& r3,
                                        uint32_t addr) {
    asm volatile("ldmatrix.sync.aligned.m8n8.x4.shared.b16 {%0,%1,%2,%3}, [%4];\n"
                 : "=r"(r0), "=r"(r1), "=r"(r2), "=r"(r3) : "r"(addr));
}
__device__ __forceinline__ float tf32_round(float x) {
    uint32_t r;
    asm volatile("cvt.rna.tf32.f32 %0, %1;\n" : "=r"(r) : "f"(x));
    return __uint_as_float(r);
}
__device__ __forceinline__ void mma_tf32(float& d0, float& d1, float& d2, float& d3,
                                         uint32_t a0, uint32_t a1, uint32_t a2, uint32_t a3,
                                         uint32_t b0, uint32_t b1) {
    asm volatile(
        "mma.sync.aligned.m16n8k8.row.col.f32.tf32.tf32.f32 "
        "{%0,%1,%2,%3}, {%4,%5,%6,%7}, {%8,%9}, {%0,%1,%2,%3};\n"
        : "+f"(d0), "+f"(d1), "+f"(d2), "+f"(d3)
        : "r"(a0), "r"(a1), "r"(a2), "r"(a3), "r"(b0), "r"(b1));
}

// ---------------------------------------------------------------------------
// Stage 0: ONE merged tf32 rounding pass over all 7 tensors.
// Layout: [q | k | v] (NA4 each) then [wq | wk | wv | wf] (NW4 each).
// ---------------------------------------------------------------------------
static constexpr int NA4 = (MM * Dd) / 4;   // 1048576
static constexpr int NW4 = (Dd * Dd) / 4;   // 262144
static constexpr int NTOT4 = 3 * NA4 + 4 * NW4;   // 4194304

struct RoundArgs {
    const float4* src[7];
    float4* dst[7];
};

__global__ void round_all_kernel(RoundArgs args)
{
    int i = blockIdx.x * blockDim.x + threadIdx.x;
    if (i >= NTOT4) return;
    int t, off;
    if (i < 3 * NA4) { t = i / NA4; off = i - t * NA4; }
    else { int j = i - 3 * NA4; t = 3 + j / NW4; off = j - (t - 3) * NW4; }
    float4 v = args.src[t][off];
    v.x = tf32_round(v.x);
    v.y = tf32_round(v.y);
    v.z = tf32_round(v.z);
    v.w = tf32_round(v.w);
    args.dst[t][off] = v;
}

// ---------------------------------------------------------------------------
// GEMM mainloop: 128x128 tile, BK=16, 3-stage cp.async pipeline, cvt-free.
// Dynamic smem: [As x3 stages | Bs x3 stages], one syncthreads per iter.
// ---------------------------------------------------------------------------
#define GBM 128
#define GBN 128
#define GBK 16
#define GSTR 20
#define GTILE_FLOATS (GBM * GSTR)          // 2560
#define GTILE_BYTES (GTILE_FLOATS * 4)     // 10240
#define GSTAGES 3
#define GEMM_SMEM_BYTES (GSTAGES * 2 * GTILE_BYTES)   // 61440

struct GemmCtx {
    float acc[4][4][4];
};

__device__ __forceinline__ void gemm_mainloop(
    const float* __restrict__ A, const float* __restrict__ W,
    int m0, int n0, int K, float* As, float* Bs, GemmCtx& ctx)
{
    const int tid  = threadIdx.x;
    const int lane = tid & 31;
    const int wid  = tid >> 5;
    const int wm   = (wid & 1) * 64;
    const int wn   = (wid >> 1) * 32;

    const uint32_t sA = cvta_smem(As);
    const uint32_t sB = cvta_smem(Bs);

    const int lr0 = tid >> 2;
    const int lg  = (tid & 3) * 4;
    const float* Ap0 = A + (size_t)(m0 + lr0) * K + lg;
    const float* Ap1 = A + (size_t)(m0 + lr0 + 64) * K + lg;
    const float* Wp0 = W + (size_t)(n0 + lr0) * K + lg;
    const float* Wp1 = W + (size_t)(n0 + lr0 + 64) * K + lg;
    const uint32_t dA0 = sA + (uint32_t)((lr0 * GSTR + lg) * 4);
    const uint32_t dA1 = sA + (uint32_t)(((lr0 + 64) * GSTR + lg) * 4);
    const uint32_t dB0 = sB + (uint32_t)((lr0 * GSTR + lg) * 4);
    const uint32_t dB1 = sB + (uint32_t)(((lr0 + 64) * GSTR + lg) * 4);

    const int g       = lane >> 3;
    const int glr     = lane & 7;
    const int row_add = ((g >> 1) << 3) + glr;
    const int koff    = (g & 1) << 2;
    const uint32_t aBase = sA + (uint32_t)(((wm + row_add) * GSTR + koff) * 4);
    const uint32_t bBase = sB + (uint32_t)(((wn + row_add) * GSTR + koff) * 4);

#pragma unroll
    for (int i = 0; i < 4; i++)
#pragma unroll
        for (int j = 0; j < 4; j++)
#pragma unroll
            for (int c = 0; c < 4; c++) ctx.acc[i][j][c] = 0.f;

    const int NSTAGE = K / GBK;   // 64

    // prologue: stages 0,1
#pragma unroll
    for (int s = 0; s < GSTAGES - 1; s++) {
        const int k0 = s * GBK;
        const uint32_t bo = (uint32_t)(s * GTILE_BYTES);
        cp_async16(dA0 + bo, Ap0 + k0);
        cp_async16(dA1 + bo, Ap1 + k0);
        cp_async16(dB0 + bo, Wp0 + k0);
        cp_async16(dB1 + bo, Wp1 + k0);
        cp_commit();
    }

    for (int kt = 0; kt < NSTAGE; kt++) {
        if (kt + 1 < NSTAGE) cp_wait1(); else cp_wait0();
        __syncthreads();   // stage kt visible to all; all warps done with iter kt-1

        if (kt + 2 < NSTAGE) {
            const int k0 = (kt + 2) * GBK;
            const uint32_t bo = (uint32_t)(((kt + 2) % GSTAGES) * GTILE_BYTES);
            cp_async16(dA0 + bo, Ap0 + k0);
            cp_async16(dA1 + bo, Ap1 + k0);
            cp_async16(dB0 + bo, Wp0 + k0);
            cp_async16(dB1 + bo, Wp1 + k0);
            cp_commit();
        }

        const uint32_t bo = (uint32_t)((kt % GSTAGES) * GTILE_BYTES);
#pragma unroll
        for (int ks = 0; ks < 2; ks++) {
            const uint32_t ao = aBase + bo + (uint32_t)(ks * 32);
            const uint32_t bb = bBase + bo + (uint32_t)(ks * 32);

            uint32_t af[4][4], bf[4][2];
#pragma unroll
            for (int mt = 0; mt < 4; mt++) {
                uint32_t r0, r1, r2, r3;
                ldsm_x4(r0, r1, r2, r3, ao + (uint32_t)(mt * 16 * GSTR * 4));
                af[mt][0] = r0;
                af[mt][1] = r2;
                af[mt][2] = r1;
                af[mt][3] = r3;
            }
#pragma unroll
            for (int p = 0; p < 2; p++) {
                uint32_t r0, r1, r2, r3;
                ldsm_x4(r0, r1, r2, r3, bb + (uint32_t)(p * 16 * GSTR * 4));
                bf[2 * p][0]     = r0;
                bf[2 * p][1]     = r1;
                bf[2 * p + 1][0] = r2;
                bf[2 * p + 1][1] = r3;
            }
#pragma unroll
            for (int mt = 0; mt < 4; mt++)
#pragma unroll
                for (int nt = 0; nt < 4; nt++)
                    mma_tf32(ctx.acc[mt][nt][0], ctx.acc[mt][nt][1],
                             ctx.acc[mt][nt][2], ctx.acc[mt][nt][3],
                             af[mt][0], af[mt][1], af[mt][2], af[mt][3],
                             bf[nt][0], bf[nt][1]);
        }
    }
}

// ---------------------------------------------------------------------------
// Merged QKV projection. grid.z: 0=Q, 1=K, 2=V^T. All outputs tf32-rounded.
// ---------------------------------------------------------------------------
__global__ __launch_bounds__(256, 2)
void qkv_gemm(const float* __restrict__ q, const float* __restrict__ k,
              const float* __restrict__ v,
              const float* __restrict__ wq, const float* __restrict__ wk,
              const float* __restrict__ wv,
              const float* __restrict__ bq, const float* __restrict__ bk,
              const float* __restrict__ bv,
              float* __restrict__ Qout, float* __restrict__ Kh,
              float* __restrict__ VT)
{
    extern __shared__ __align__(16) float gsm[];
    float* As = gsm;
    float* Bs = gsm + GSTAGES * GTILE_FLOATS;

    const int z  = blockIdx.z;
    const int m0 = blockIdx.y * GBM;
    const int n0 = blockIdx.x * GBN;

    const float* A    = (z == 0) ? q  : (z == 1) ? k  : v;
    const float* W    = (z == 0) ? wq : (z == 1) ? wk : wv;
    const float* bias = (z == 0) ? bq : (z == 1) ? bk : bv;

    GemmCtx ctx;
    gemm_mainloop(A, W, m0, n0, Dd, As, Bs, ctx);

    const int lane = threadIdx.x & 31;
    const int wid  = threadIdx.x >> 5;
    const int wm   = (wid & 1) * 64;
    const int wn   = (wid >> 1) * 32;

#pragma unroll
    for (int mt = 0; mt < 4; mt++) {
        const int row = m0 + wm + mt * 16 + (lane >> 2);
#pragma unroll
        for (int nt = 0; nt < 4; nt++) {
            const int col = n0 + wn + nt * 8 + (lane & 3) * 2;
            const float b0 = bias[col], b1 = bias[col + 1];
            float v00 = tf32_round(ctx.acc[mt][nt][0] + b0);
            float v01 = tf32_round(ctx.acc[mt][nt][1] + b1);
            float v10 = tf32_round(ctx.acc[mt][nt][2] + b0);
            float v11 = tf32_round(ctx.acc[mt][nt][3] + b1);
            if (z == 0) {
                *(float2*)&Qout[(size_t)row * Dd + col]       = make_float2(v00, v01);
                *(float2*)&Qout[(size_t)(row + 8) * Dd + col] = make_float2(v10, v11);
            } else if (z == 1) {
                *(float2*)&Kh[(size_t)row * Dd + col]       = make_float2(v00, v01);
                *(float2*)&Kh[(size_t)(row + 8) * Dd + col] = make_float2(v10, v11);
            } else {
                const int b_  = row >> 11, s0 = row & 2047;
                const int h_  = col >> 6,  d0 = col & 63;
                float* base = VT + (((size_t)b_ * Hh + h_) * DP + d0) * Ss + s0;
                base[0]      = v00;
                base[Ss]     = v01;
                base[8]      = v10;
                base[Ss + 8] = v11;
            }
        }
    }
}

// fc output projection
__global__ __launch_bounds__(256, 2)
void fc_gemm(const float* __restrict__ A, const float* __restrict__ W,
             const float* __restrict__ bias, float* __restrict__ C)
{
    extern __shared__ __align__(16) float gsm[];
    float* As = gsm;
    float* Bs = gsm + GSTAGES * GTILE_FLOATS;

    const int m0 = blockIdx.y * GBM;
    const int n0 = blockIdx.x * GBN;

    GemmCtx ctx;
    gemm_mainloop(A, W, m0, n0, Dd, As, Bs, ctx);

    const int lane = threadIdx.x & 31;
    const int wid  = threadIdx.x >> 5;
    const int wm   = (wid & 1) * 64;
    const int wn   = (wid >> 1) * 32;

#pragma unroll
    for (int mt = 0; mt < 4; mt++) {
        const int row = m0 + wm + mt * 16 + (lane >> 2);
#pragma unroll
        for (int nt = 0; nt < 4; nt++) {
            const int col = n0 + wn + nt * 8 + (lane & 3) * 2;
            const float b0 = bias[col], b1 = bias[col + 1];
            *(float2*)&C[(size_t)row * Dd + col] =
                make_float2(ctx.acc[mt][nt][0] + b0, ctx.acc[mt][nt][1] + b1);
            *(float2*)&C[(size_t)(row + 8) * Dd + col] =
                make_float2(ctx.acc[mt][nt][2] + b0, ctx.acc[mt][nt][3] + b1);
        }
    }
}

// ---------------------------------------------------------------------------
// Tensor-core flash attention (unchanged from R11 passing kernel).
// ---------------------------------------------------------------------------
#define FSTR 68
#define KV_TILE (64 * FSTR)
#define FLASH_SMEM_FLOATS (4 * KV_TILE + 64 * FSTR)
#define FLASH_SMEM_BYTES (FLASH_SMEM_FLOATS * 4)   // 87040

__global__ __launch_bounds__(128, 2)
void flash_attn_tc(const float* __restrict__ Qp, const float* __restrict__ Kh_g,
                   const float* __restrict__ VT_g, const float* __restrict__ mask,
                   float* __restrict__ Out, float* __restrict__ FCin)
{
    extern __shared__ float fsm[];
    float* Khb  = fsm;
    float* Vtb  = Khb + 2 * KV_TILE;
    float* Pbuf = Vtb + 2 * KV_TILE;

    const uint32_t sKh = cvta_smem(Khb);
    const uint32_t sVt = cvta_smem(Vtb);
    const uint32_t sP  = cvta_smem(Pbuf);

    const int tid  = threadIdx.x;
    const int lane = tid & 31;
    const int wid  = tid >> 5;
    const int wm   = wid * 16;
    const int q0   = blockIdx.x * 64;
    const int h    = blockIdx.y;
    const int b    = blockIdx.z;

    const float* Qg  = Qp   + ((size_t)b * Ss + q0) * Dd + h * DP;
    const float* Khg = Kh_g + ((size_t)b * Ss) * Dd + h * DP;
    const float* VTg = VT_g + ((size_t)b * Hh + h) * DP * Ss;
    const float* Mg  = mask + (((size_t)b * Hh + h) * Ss + q0) * Ss;

    const int g       = lane >> 3;
    const int glr     = lane & 7;
    const int row_add = ((g >> 1) << 3) + glr;
    const int koff    = (g & 1) << 2;

    const int rq = lane >> 2;
    const int cq = lane & 3;

    const int lrow = tid >> 4;
    const int lcol = tid & 15;

    {
#pragma unroll
        for (int i = 0; i < 8; i++) {
            int row = lrow + 8 * i;
            uint32_t so = (uint32_t)((row * FSTR + lcol * 4) * 4);
            cp_async16(sKh + so, Khg + (size_t)row * Dd + lcol * 4);
            cp_async16(sVt + so, VTg + (size_t)row * Ss + lcol * 4);
        }
        cp_commit();
    }

#pragma unroll
    for (int i = 0; i < 8; i++) {
        int id = tid + 128 * i;
        int row = id >> 4, col = id & 15;
        float4 v = *(const float4*)(Qg + (size_t)row * Dd + col * 4);
        *(float4*)&Pbuf[row * FSTR + col * 4] = v;
    }
    __syncthreads();

    uint32_t Qh[8][4];
    {
        const uint32_t base = sP + (uint32_t)(((wm + row_add) * FSTR + koff) * 4);
#pragma unroll
        for (int ks = 0; ks < 8; ks++) {
            uint32_t r0, r1, r2, r3;
            ldsm_x4(r0, r1, r2, r3, base + (uint32_t)(ks * 32));
            Qh[ks][0] = r0;
            Qh[ks][1] = r2;
            Qh[ks][2] = r1;
            Qh[ks][3] = r3;
        }
    }

    float O[8][4];
#pragma unroll
    for (int nt = 0; nt < 8; nt++)
#pragma unroll
        for (int c = 0; c < 4; c++) O[nt][c] = 0.f;
    float m0r = NEG_INF, m1r = NEG_INF, l0r = 0.f, l1r = 0.f;

    for (int kt = 0; kt < 32; kt++) {
        cp_wait0();
        __syncthreads();

        if (kt + 1 < 32) {
            const uint32_t bo = (uint32_t)(((kt + 1) & 1) * KV_TILE * 4);
            const float* khg = Khg + (size_t)(kt + 1) * 64 * Dd;
            const float* vtg = VTg + (size_t)(kt + 1) * 64;
#pragma unroll
            for (int i = 0; i < 8; i++) {
                int row = lrow + 8 * i;
                uint32_t so = (uint32_t)((row * FSTR + lcol * 4) * 4);
                cp_async16(sKh + bo + so, khg + (size_t)row * Dd + lcol * 4);
                cp_async16(sVt + bo + so, vtg + (size_t)row * Ss + lcol * 4);
            }
            cp_commit();
        }

        float2 mk0[8], mk1[8];
        {
            const float* mr0 = Mg + (size_t)(wm + rq) * Ss + kt * 64 + 2 * cq;
            const float* mr1 = mr0 + 8 * Ss;
#pragma unroll
            for (int nt = 0; nt < 8; nt++) {
                mk0[nt] = *(const float2*)(mr0 + nt * 8);
                mk1[nt] = *(const float2*)(mr1 + nt * 8);
            }
        }

        float S[8][4];
#pragma unroll
        for (int nt = 0; nt < 8; nt++)
#pragma unroll
            for (int c = 0; c < 4; c++) S[nt][c] = 0.f;

        const uint32_t khb = sKh + (uint32_t)((kt & 1) * KV_TILE * 4)
                           + (uint32_t)((row_add * FSTR + koff) * 4);
#pragma unroll
        for (int ks = 0; ks < 8; ks++) {
#pragma unroll
            for (int p = 0; p < 4; p++) {
                const uint32_t off = (uint32_t)((p * 16 * FSTR) * 4 + ks * 32);
                uint32_t h0, h1, h2, h3;
                ldsm_x4(h0, h1, h2, h3, khb + off);
                const int n0 = 2 * p, n1 = 2 * p + 1;
                mma_tf32(S[n0][0], S[n0][1], S[n0][2], S[n0][3],
                         Qh[ks][0], Qh[ks][1], Qh[ks][2], Qh[ks][3], h0, h1);
                mma_tf32(S[n1][0], S[n1][1], S[n1][2], S[n1][3],
                         Qh[ks][0], Qh[ks][1], Qh[ks][2], Qh[ks][3], h2, h3);
            }
        }

        float rm0 = NEG_INF, rm1 = NEG_INF;
#pragma unroll
        for (int nt = 0; nt < 8; nt++) {
            S[nt][0] = S[nt][0] * 0.125f + mk0[nt].x * (-1e9f);
            S[nt][1] = S[nt][1] * 0.125f + mk0[nt].y * (-1e9f);
            S[nt][2] = S[nt][2] * 0.125f + mk1[nt].x * (-1e9f);
            S[nt][3] = S[nt][3] * 0.125f + mk1[nt].y * (-1e9f);
            rm0 = fmaxf(rm0, fmaxf(S[nt][0], S[nt][1]));
            rm1 = fmaxf(rm1, fmaxf(S[nt][2], S[nt][3]));
        }
        rm0 = fmaxf(rm0, __shfl_xor_sync(0xffffffffu, rm0, 1));
        rm0 = fmaxf(rm0, __shfl_xor_sync(0xffffffffu, rm0, 2));
        rm1 = fmaxf(rm1, __shfl_xor_sync(0xffffffffu, rm1, 1));
        rm1 = fmaxf(rm1, __shfl_xor_sync(0xffffffffu, rm1, 2));

        const float nm0 = fmaxf(m0r, rm0);
        const float nm1 = fmaxf(m1r, rm1);
        const float sc0 = __expf(m0r - nm0);
        const float sc1 = __expf(m1r - nm1);
        m0r = nm0; m1r = nm1;

        float rs0 = 0.f, rs1 = 0.f;
#pragma unroll
        for (int nt = 0; nt < 8; nt++) {
            S[nt][0] = __expf(S[nt][0] - nm0);
            S[nt][1] = __expf(S[nt][1] - nm0);
            S[nt][2] = __expf(S[nt][2] - nm1);
            S[nt][3] = __expf(S[nt][3] - nm1);
            rs0 += S[nt][0] + S[nt][1];
            rs1 += S[nt][2] + S[nt][3];
        }
        rs0 += __shfl_xor_sync(0xffffffffu, rs0, 1);
        rs0 += __shfl_xor_sync(0xffffffffu, rs0, 2);
        rs1 += __shfl_xor_sync(0xffffffffu, rs1, 1);
        rs1 += __shfl_xor_sync(0xffffffffu, rs1, 2);
        l0r = l0r * sc0 + rs0;
        l1r = l1r * sc1 + rs1;

#pragma unroll
        for (int nt = 0; nt < 8; nt++) {
            O[nt][0] *= sc0; O[nt][1] *= sc0;
            O[nt][2] *= sc1; O[nt][3] *= sc1;
        }

        {
            float* p0 = Pbuf + (wm + rq) * FSTR + 2 * cq;
            float* p1 = p0 + 8 * FSTR;
#pragma unroll
            for (int nt = 0; nt < 8; nt++) {
                *(float2*)(p0 + nt * 8) =
                    make_float2(tf32_round(S[nt][0]), tf32_round(S[nt][1]));
                *(float2*)(p1 + nt * 8) =
                    make_float2(tf32_round(S[nt][2]), tf32_round(S[nt][3]));
            }
        }
        __syncwarp();

        const uint32_t pb = sP + (uint32_t)(((wm + row_add) * FSTR + koff) * 4);
        const uint32_t vb = sVt + (uint32_t)((kt & 1) * KV_TILE * 4)
                          + (uint32_t)((row_add * FSTR + koff) * 4);
#pragma unroll
        for (int ks = 0; ks < 8; ks++) {
            uint32_t pr0, pr1, pr2, pr3;
            ldsm_x4(pr0, pr1, pr2, pr3, pb + (uint32_t)(ks * 32));
            uint32_t a0 = pr0, a1 = pr2, a2 = pr1, a3 = pr3;
#pragma unroll
            for (int p = 0; p < 4; p++) {
                uint32_t v0, v1, v2, v3;
                ldsm_x4(v0, v1, v2, v3, vb + (uint32_t)((p * 16 * FSTR) * 4 + ks * 32));
                const int n0 = 2 * p, n1 = 2 * p + 1;
                mma_tf32(O[n0][0], O[n0][1], O[n0][2], O[n0][3], a0, a1, a2, a3, v0, v1);
                mma_tf32(O[n1][0], O[n1][1], O[n1][2], O[n1][3], a0, a1, a2, a3, v2, v3);
            }
        }
    }

    const float inv0 = 1.f / l0r;
    const float inv1 = 1.f / l1r;
    const size_t base_off = ((size_t)b * Ss + q0 + wm + rq) * Dd + h * DP + 2 * cq;
    float* o0 = Out + base_off;
    float* o1 = o0 + (size_t)8 * Dd;
    float* f0 = FCin + base_off;
    float* f1 = f0 + (size_t)8 * Dd;
#pragma unroll
    for (int nt = 0; nt < 8; nt++) {
        float a = O[nt][0] * inv0, bb2 = O[nt][1] * inv0;
        float c = O[nt][2] * inv1, d = O[nt][3] * inv1;
        *(float2*)(o0 + nt * 8) = make_float2(a, bb2);
        *(float2*)(o1 + nt * 8) = make_float2(c, d);
        *(float2*)(f0 + nt * 8) = make_float2(tf32_round(a), tf32_round(bb2));
        *(float2*)(f1 + nt * 8) = make_float2(tf32_round(c), tf32_round(d));
    }
}

// ---------------------------------------------------------------------------
extern "C" void kernel_launch(void* const* d_in, const int* in_sizes, int n_in,
                              void* d_out, int out_size)
{
    const float* q    = (const float*)d_in[0];
    const float* k    = (const float*)d_in[1];
    const float* v    = (const float*)d_in[2];
    const float* mask = (const float*)d_in[3];
    const float* wq_w = (const float*)d_in[4];
    const float* wq_b = (const float*)d_in[5];
    const float* wk_w = (const float*)d_in[6];
    const float* wk_b = (const float*)d_in[7];
    const float* wv_w = (const float*)d_in[8];
    const float* wv_b = (const float*)d_in[9];
    const float* fc_w = (const float*)d_in[10];
    const float* fc_b = (const float*)d_in[11];

    float *pQ, *pKh, *pVT, *pScr, *pFC;
    float *pqr, *pkr, *pvr, *pwqr, *pwkr, *pwvr, *pwfr;
    cudaGetSymbolAddress((void**)&pQ, g_Qp);
    cudaGetSymbolAddress((void**)&pKh, g_Kh);
    cudaGetSymbolAddress((void**)&pVT, g_VT);
    cudaGetSymbolAddress((void**)&pScr, g_attn_scratch);
    cudaGetSymbolAddress((void**)&pFC, g_FCin);
    cudaGetSymbolAddress((void**)&pqr, g_qr);
    cudaGetSymbolAddress((void**)&pkr, g_kr);
    cudaGetSymbolAddress((void**)&pvr, g_vr);
    cudaGetSymbolAddress((void**)&pwqr, g_wqr);
    cudaGetSymbolAddress((void**)&pwkr, g_wkr);
    cudaGetSymbolAddress((void**)&pwvr, g_wvr);
    cudaGetSymbolAddress((void**)&pwfr, g_wfr);

    float* out_main = (float*)d_out;
    const size_t OUT1 = (size_t)MM * Dd;
    float* attn_out = ((size_t)out_size >= 2 * OUT1) ? (out_main + OUT1) : pScr;

    static bool attr_set = false;
    if (!attr_set) {
        cudaFuncSetAttribute(flash_attn_tc, cudaFuncAttributeMaxDynamicSharedMemorySize,
                             FLASH_SMEM_BYTES);
        cudaFuncSetAttribute(qkv_gemm, cudaFuncAttributeMaxDynamicSharedMemorySize,
                             GEMM_SMEM_BYTES);
        cudaFuncSetAttribute(fc_gemm, cudaFuncAttributeMaxDynamicSharedMemorySize,
                             GEMM_SMEM_BYTES);
        attr_set = true;
    }

    // Stage 0: one merged tf32 rounding pass
    RoundArgs ra;
    ra.src[0] = (const float4*)q;    ra.dst[0] = (float4*)pqr;
    ra.src[1] = (const float4*)k;    ra.dst[1] = (float4*)pkr;
    ra.src[2] = (const float4*)v;    ra.dst[2] = (float4*)pvr;
    ra.src[3] = (const float4*)wq_w; ra.dst[3] = (float4*)pwqr;
    ra.src[4] = (const float4*)wk_w; ra.dst[4] = (float4*)pwkr;
    ra.src[5] = (const float4*)wv_w; ra.dst[5] = (float4*)pwvr;
    ra.src[6] = (const float4*)fc_w; ra.dst[6] = (float4*)pwfr;
    round_all_kernel<<<(NTOT4 + 255) / 256, 256>>>(ra);

    qkv_gemm<<<dim3(Dd / GBN, MM / GBM, 3), 256, GEMM_SMEM_BYTES>>>(
        pqr, pkr, pvr, pwqr, pwkr, pwvr, wq_b, wk_b, wv_b, pQ, pKh, pVT);

    flash_attn_tc<<<dim3(Ss / 64, Hh, Bb), 128, FLASH_SMEM_BYTES>>>(
        pQ, pKh, pVT, mask, attn_out, pFC);

    fc_gemm<<<dim3(Dd / GBN, MM / GBM), 256, GEMM_SMEM_BYTES>>>(
        pFC, pwfr, fc_b, out_main);
}

// round 13
// speedup vs baseline: 1.0149x; 1.0149x over previous
#include <cuda_runtime.h>
#include <cstdint>

// ---------------------------------------------------------------------------
// MultiHeadAttn: B=2, S=2048, D=1024, H=16, depth=64
// Stage 0: single merged round_tf32 pre-pass (q,k,v + 4 weights).
// Stage 1: merged QKV projections, cvt-free 2-stage pipeline, ONE sync/iter.
// Stage 2: flash attention (unchanged R11): 64q CTA, 4 warps, 2 CTA/SM.
// Stage 3: fc output projection, same single-sync mainloop.
// ---------------------------------------------------------------------------

#define NEG_INF (-3.402823466e38f)

static constexpr int Bb = 2;
static constexpr int Ss = 2048;
static constexpr int Dd = 1024;
static constexpr int Hh = 16;
static constexpr int DP = 64;
static constexpr int MM = Bb * Ss;  // 4096

__device__ float g_Qp[(size_t)MM * Dd];
__device__ float g_Kh[(size_t)MM * Dd];
__device__ float g_VT[(size_t)MM * Dd];   // [B, H, DP, Ss]
__device__ float g_attn_scratch[(size_t)MM * Dd];
__device__ float g_FCin[(size_t)MM * Dd];
__device__ float g_qr[(size_t)MM * Dd];
__device__ float g_kr[(size_t)MM * Dd];
__device__ float g_vr[(size_t)MM * Dd];
__device__ float g_wqr[(size_t)Dd * Dd];
__device__ float g_wkr[(size_t)Dd * Dd];
__device__ float g_wvr[(size_t)Dd * Dd];
__device__ float g_wfr[(size_t)Dd * Dd];

// ---------------------------------------------------------------------------
// PTX helpers
// ---------------------------------------------------------------------------
__device__ __forceinline__ uint32_t cvta_smem(const void* p) {
    return (uint32_t)__cvta_generic_to_shared(p);
}
__device__ __forceinline__ void cp_async16(uint32_t dst, const void* src) {
    asm volatile("cp.async.cg.shared.global [%0], [%1], 16;\n" :: "r"(dst), "l"(src));
}
__device__ __forceinline__ void cp_commit() {
    asm volatile("cp.async.commit_group;\n");
}
__device__ __forceinline__ void cp_wait0() {
    asm volatile("cp.async.wait_group 0;\n");
}
__device__ __forceinline__ void ldsm_x4(uint32_t& r0, uint32_t& r1, uint32_t& r2, uint32_t& r3,
                                        uint32_t addr) {
    asm volatile("ldmatrix.sync.aligned.m8n8.x4.shared.b16 {%0,%1,%2,%3}, [%4];\n"
                 : "=r"(r0), "=r"(r1), "=r"(r2), "=r"(r3) : "r"(addr));
}
__device__ __forceinline__ float tf32_round(float x) {
    uint32_t r;
    asm volatile("cvt.rna.tf32.f32 %0, %1;\n" : "=r"(r) : "f"(x));
    return __uint_as_float(r);
}
__device__ __forceinline__ void mma_tf32(float& d0, float& d1, float& d2, float& d3,
                                         uint32_t a0, uint32_t a1, uint32_t a2, uint32_t a3,
                                         uint32_t b0, uint32_t b1) {
    asm volatile(
        "mma.sync.aligned.m16n8k8.row.col.f32.tf32.tf32.f32 "
        "{%0,%1,%2,%3}, {%4,%5,%6,%7}, {%8,%9}, {%0,%1,%2,%3};\n"
        : "+f"(d0), "+f"(d1), "+f"(d2), "+f"(d3)
        : "r"(a0), "r"(a1), "r"(a2), "r"(a3), "r"(b0), "r"(b1));
}

// ---------------------------------------------------------------------------
// Stage 0: ONE merged tf32 rounding pass over all 7 tensors.
// ---------------------------------------------------------------------------
static constexpr int NA4 = (MM * Dd) / 4;   // 1048576
static constexpr int NW4 = (Dd * Dd) / 4;   // 262144
static constexpr int NTOT4 = 3 * NA4 + 4 * NW4;   // 4194304

struct RoundArgs {
    const float4* src[7];
    float4* dst[7];
};

__global__ void round_all_kernel(RoundArgs args)
{
    int i = blockIdx.x * blockDim.x + threadIdx.x;
    if (i >= NTOT4) return;
    int t, off;
    if (i < 3 * NA4) { t = i / NA4; off = i - t * NA4; }
    else { int j = i - 3 * NA4; t = 3 + j / NW4; off = j - (t - 3) * NW4; }
    float4 v = args.src[t][off];
    v.x = tf32_round(v.x);
    v.y = tf32_round(v.y);
    v.z = tf32_round(v.z);
    v.w = tf32_round(v.w);
    args.dst[t][off] = v;
}

// ---------------------------------------------------------------------------
// GEMM mainloop: 128x128 tile, BK=16, 2-stage, cvt-free, ONE sync per iter.
// Safety: prefetch at iter kt writes stage (kt+1)&1, last read at iter kt-1;
// the top-of-kt sync orders all warps past iter kt-1. Tile visibility at iter
// kt needs only each thread's own wait_group 0 + the top sync.
// ---------------------------------------------------------------------------
#define GBM 128
#define GBN 128
#define GBK 16
#define GSTR 20
#define GTILE_BYTES (GBM * GSTR * 4)

struct GemmCtx {
    float acc[4][4][4];
};

__device__ __forceinline__ void gemm_mainloop(
    const float* __restrict__ A, const float* __restrict__ W,
    int m0, int n0, int K, float (*As)[GBM * GSTR], float (*Bs)[GBN * GSTR],
    GemmCtx& ctx)
{
    const int tid  = threadIdx.x;
    const int lane = tid & 31;
    const int wid  = tid >> 5;
    const int wm   = (wid & 1) * 64;
    const int wn   = (wid >> 1) * 32;

    const uint32_t sA = cvta_smem(As);
    const uint32_t sB = cvta_smem(Bs);

    const int lr0 = tid >> 2;
    const int lg  = (tid & 3) * 4;
    const float* Ap0 = A + (size_t)(m0 + lr0) * K + lg;
    const float* Ap1 = A + (size_t)(m0 + lr0 + 64) * K + lg;
    const float* Wp0 = W + (size_t)(n0 + lr0) * K + lg;
    const float* Wp1 = W + (size_t)(n0 + lr0 + 64) * K + lg;
    const uint32_t dA0 = sA + (uint32_t)((lr0 * GSTR + lg) * 4);
    const uint32_t dA1 = sA + (uint32_t)(((lr0 + 64) * GSTR + lg) * 4);
    const uint32_t dB0 = sB + (uint32_t)((lr0 * GSTR + lg) * 4);
    const uint32_t dB1 = sB + (uint32_t)(((lr0 + 64) * GSTR + lg) * 4);

    const int g       = lane >> 3;
    const int glr     = lane & 7;
    const int row_add = ((g >> 1) << 3) + glr;
    const int koff    = (g & 1) << 2;
    const uint32_t aBase = sA + (uint32_t)(((wm + row_add) * GSTR + koff) * 4);
    const uint32_t bBase = sB + (uint32_t)(((wn + row_add) * GSTR + koff) * 4);

#pragma unroll
    for (int i = 0; i < 4; i++)
#pragma unroll
        for (int j = 0; j < 4; j++)
#pragma unroll
            for (int c = 0; c < 4; c++) ctx.acc[i][j][c] = 0.f;

    const int NSTAGE = K / GBK;

    cp_async16(dA0, Ap0); cp_async16(dA1, Ap1);
    cp_async16(dB0, Wp0); cp_async16(dB1, Wp1);
    cp_commit();

    for (int kt = 0; kt < NSTAGE; kt++) {
        cp_wait0();
        __syncthreads();   // tile kt visible; all warps past iter kt-1 reads

        if (kt + 1 < NSTAGE) {
            const int k0 = (kt + 1) * GBK;
            const uint32_t bo = (uint32_t)(((kt + 1) & 1) * GTILE_BYTES);
            cp_async16(dA0 + bo, Ap0 + k0);
            cp_async16(dA1 + bo, Ap1 + k0);
            cp_async16(dB0 + bo, Wp0 + k0);
            cp_async16(dB1 + bo, Wp1 + k0);
            cp_commit();
        }

        const uint32_t bo = (uint32_t)((kt & 1) * GTILE_BYTES);
#pragma unroll
        for (int ks = 0; ks < 2; ks++) {
            const uint32_t ao = aBase + bo + (uint32_t)(ks * 32);
            const uint32_t bb = bBase + bo + (uint32_t)(ks * 32);

            uint32_t af[4][4], bf[4][2];
#pragma unroll
            for (int mt = 0; mt < 4; mt++) {
                uint32_t r0, r1, r2, r3;
                ldsm_x4(r0, r1, r2, r3, ao + (uint32_t)(mt * 16 * GSTR * 4));
                af[mt][0] = r0;
                af[mt][1] = r2;
                af[mt][2] = r1;
                af[mt][3] = r3;
            }
#pragma unroll
            for (int p = 0; p < 2; p++) {
                uint32_t r0, r1, r2, r3;
                ldsm_x4(r0, r1, r2, r3, bb + (uint32_t)(p * 16 * GSTR * 4));
                bf[2 * p][0]     = r0;
                bf[2 * p][1]     = r1;
                bf[2 * p + 1][0] = r2;
                bf[2 * p + 1][1] = r3;
            }
#pragma unroll
            for (int mt = 0; mt < 4; mt++)
#pragma unroll
                for (int nt = 0; nt < 4; nt++)
                    mma_tf32(ctx.acc[mt][nt][0], ctx.acc[mt][nt][1],
                             ctx.acc[mt][nt][2], ctx.acc[mt][nt][3],
                             af[mt][0], af[mt][1], af[mt][2], af[mt][3],
                             bf[nt][0], bf[nt][1]);
        }
        // no bottom sync: next iteration's top sync provides the ordering
    }
}

// ---------------------------------------------------------------------------
// Merged QKV projection. grid.z: 0=Q, 1=K, 2=V^T. All outputs tf32-rounded.
// ---------------------------------------------------------------------------
__global__ __launch_bounds__(256, 2)
void qkv_gemm(const float* __restrict__ q, const float* __restrict__ k,
              const float* __restrict__ v,
              const float* __restrict__ wq, const float* __restrict__ wk,
              const float* __restrict__ wv,
              const float* __restrict__ bq, const float* __restrict__ bk,
              const float* __restrict__ bv,
              float* __restrict__ Qout, float* __restrict__ Kh,
              float* __restrict__ VT)
{
    __shared__ __align__(16) float As[2][GBM * GSTR];
    __shared__ __align__(16) float Bs[2][GBN * GSTR];

    const int z  = blockIdx.z;
    const int m0 = blockIdx.y * GBM;
    const int n0 = blockIdx.x * GBN;

    const float* A    = (z == 0) ? q  : (z == 1) ? k  : v;
    const float* W    = (z == 0) ? wq : (z == 1) ? wk : wv;
    const float* bias = (z == 0) ? bq : (z == 1) ? bk : bv;

    GemmCtx ctx;
    gemm_mainloop(A, W, m0, n0, Dd, As, Bs, ctx);

    const int lane = threadIdx.x & 31;
    const int wid  = threadIdx.x >> 5;
    const int wm   = (wid & 1) * 64;
    const int wn   = (wid >> 1) * 32;

#pragma unroll
    for (int mt = 0; mt < 4; mt++) {
        const int row = m0 + wm + mt * 16 + (lane >> 2);
#pragma unroll
        for (int nt = 0; nt < 4; nt++) {
            const int col = n0 + wn + nt * 8 + (lane & 3) * 2;
            const float b0 = bias[col], b1 = bias[col + 1];
            float v00 = tf32_round(ctx.acc[mt][nt][0] + b0);
            float v01 = tf32_round(ctx.acc[mt][nt][1] + b1);
            float v10 = tf32_round(ctx.acc[mt][nt][2] + b0);
            float v11 = tf32_round(ctx.acc[mt][nt][3] + b1);
            if (z == 0) {
                *(float2*)&Qout[(size_t)row * Dd + col]       = make_float2(v00, v01);
                *(float2*)&Qout[(size_t)(row + 8) * Dd + col] = make_float2(v10, v11);
            } else if (z == 1) {
                *(float2*)&Kh[(size_t)row * Dd + col]       = make_float2(v00, v01);
                *(float2*)&Kh[(size_t)(row + 8) * Dd + col] = make_float2(v10, v11);
            } else {
                const int b_  = row >> 11, s0 = row & 2047;
                const int h_  = col >> 6,  d0 = col & 63;
                float* base = VT + (((size_t)b_ * Hh + h_) * DP + d0) * Ss + s0;
                base[0]      = v00;
                base[Ss]     = v01;
                base[8]      = v10;
                base[Ss + 8] = v11;
            }
        }
    }
}

// fc output projection
__global__ __launch_bounds__(256, 2)
void fc_gemm(const float* __restrict__ A, const float* __restrict__ W,
             const float* __restrict__ bias, float* __restrict__ C)
{
    __shared__ __align__(16) float As[2][GBM * GSTR];
    __shared__ __align__(16) float Bs[2][GBN * GSTR];

    const int m0 = blockIdx.y * GBM;
    const int n0 = blockIdx.x * GBN;

    GemmCtx ctx;
    gemm_mainloop(A, W, m0, n0, Dd, As, Bs, ctx);

    const int lane = threadIdx.x & 31;
    const int wid  = threadIdx.x >> 5;
    const int wm   = (wid & 1) * 64;
    const int wn   = (wid >> 1) * 32;

#pragma unroll
    for (int mt = 0; mt < 4; mt++) {
        const int row = m0 + wm + mt * 16 + (lane >> 2);
#pragma unroll
        for (int nt = 0; nt < 4; nt++) {
            const int col = n0 + wn + nt * 8 + (lane & 3) * 2;
            const float b0 = bias[col], b1 = bias[col + 1];
            *(float2*)&C[(size_t)row * Dd + col] =
                make_float2(ctx.acc[mt][nt][0] + b0, ctx.acc[mt][nt][1] + b1);
            *(float2*)&C[(size_t)(row + 8) * Dd + col] =
                make_float2(ctx.acc[mt][nt][2] + b0, ctx.acc[mt][nt][3] + b1);
        }
    }
}

// ---------------------------------------------------------------------------
// Tensor-core flash attention (unchanged from R11 passing kernel).
// ---------------------------------------------------------------------------
#define FSTR 68
#define KV_TILE (64 * FSTR)
#define FLASH_SMEM_FLOATS (4 * KV_TILE + 64 * FSTR)
#define FLASH_SMEM_BYTES (FLASH_SMEM_FLOATS * 4)   // 87040

__global__ __launch_bounds__(128, 2)
void flash_attn_tc(const float* __restrict__ Qp, const float* __restrict__ Kh_g,
                   const float* __restrict__ VT_g, const float* __restrict__ mask,
                   float* __restrict__ Out, float* __restrict__ FCin)
{
    extern __shared__ float fsm[];
    float* Khb  = fsm;
    float* Vtb  = Khb + 2 * KV_TILE;
    float* Pbuf = Vtb + 2 * KV_TILE;

    const uint32_t sKh = cvta_smem(Khb);
    const uint32_t sVt = cvta_smem(Vtb);
    const uint32_t sP  = cvta_smem(Pbuf);

    const int tid  = threadIdx.x;
    const int lane = tid & 31;
    const int wid  = tid >> 5;
    const int wm   = wid * 16;
    const int q0   = blockIdx.x * 64;
    const int h    = blockIdx.y;
    const int b    = blockIdx.z;

    const float* Qg  = Qp   + ((size_t)b * Ss + q0) * Dd + h * DP;
    const float* Khg = Kh_g + ((size_t)b * Ss) * Dd + h * DP;
    const float* VTg = VT_g + ((size_t)b * Hh + h) * DP * Ss;
    const float* Mg  = mask + (((size_t)b * Hh + h) * Ss + q0) * Ss;

    const int g       = lane >> 3;
    const int glr     = lane & 7;
    const int row_add = ((g >> 1) << 3) + glr;
    const int koff    = (g & 1) << 2;

    const int rq = lane >> 2;
    const int cq = lane & 3;

    const int lrow = tid >> 4;
    const int lcol = tid & 15;

    {
#pragma unroll
        for (int i = 0; i < 8; i++) {
            int row = lrow + 8 * i;
            uint32_t so = (uint32_t)((row * FSTR + lcol * 4) * 4);
            cp_async16(sKh + so, Khg + (size_t)row * Dd + lcol * 4);
            cp_async16(sVt + so, VTg + (size_t)row * Ss + lcol * 4);
        }
        cp_commit();
    }

#pragma unroll
    for (int i = 0; i < 8; i++) {
        int id = tid + 128 * i;
        int row = id >> 4, col = id & 15;
        float4 v = *(const float4*)(Qg + (size_t)row * Dd + col * 4);
        *(float4*)&Pbuf[row * FSTR + col * 4] = v;
    }
    __syncthreads();

    uint32_t Qh[8][4];
    {
        const uint32_t base = sP + (uint32_t)(((wm + row_add) * FSTR + koff) * 4);
#pragma unroll
        for (int ks = 0; ks < 8; ks++) {
            uint32_t r0, r1, r2, r3;
            ldsm_x4(r0, r1, r2, r3, base + (uint32_t)(ks * 32));
            Qh[ks][0] = r0;
            Qh[ks][1] = r2;
            Qh[ks][2] = r1;
            Qh[ks][3] = r3;
        }
    }

    float O[8][4];
#pragma unroll
    for (int nt = 0; nt < 8; nt++)
#pragma unroll
        for (int c = 0; c < 4; c++) O[nt][c] = 0.f;
    float m0r = NEG_INF, m1r = NEG_INF, l0r = 0.f, l1r = 0.f;

    for (int kt = 0; kt < 32; kt++) {
        cp_wait0();
        __syncthreads();

        if (kt + 1 < 32) {
            const uint32_t bo = (uint32_t)(((kt + 1) & 1) * KV_TILE * 4);
            const float* khg = Khg + (size_t)(kt + 1) * 64 * Dd;
            const float* vtg = VTg + (size_t)(kt + 1) * 64;
#pragma unroll
            for (int i = 0; i < 8; i++) {
                int row = lrow + 8 * i;
                uint32_t so = (uint32_t)((row * FSTR + lcol * 4) * 4);
                cp_async16(sKh + bo + so, khg + (size_t)row * Dd + lcol * 4);
                cp_async16(sVt + bo + so, vtg + (size_t)row * Ss + lcol * 4);
            }
            cp_commit();
        }

        float2 mk0[8], mk1[8];
        {
            const float* mr0 = Mg + (size_t)(wm + rq) * Ss + kt * 64 + 2 * cq;
            const float* mr1 = mr0 + 8 * Ss;
#pragma unroll
            for (int nt = 0; nt < 8; nt++) {
                mk0[nt] = *(const float2*)(mr0 + nt * 8);
                mk1[nt] = *(const float2*)(mr1 + nt * 8);
            }
        }

        float S[8][4];
#pragma unroll
        for (int nt = 0; nt < 8; nt++)
#pragma unroll
            for (int c = 0; c < 4; c++) S[nt][c] = 0.f;

        const uint32_t khb = sKh + (uint32_t)((kt & 1) * KV_TILE * 4)
                           + (uint32_t)((row_add * FSTR + koff) * 4);
#pragma unroll
        for (int ks = 0; ks < 8; ks++) {
#pragma unroll
            for (int p = 0; p < 4; p++) {
                const uint32_t off = (uint32_t)((p * 16 * FSTR) * 4 + ks * 32);
                uint32_t h0, h1, h2, h3;
                ldsm_x4(h0, h1, h2, h3, khb + off);
                const int n0 = 2 * p, n1 = 2 * p + 1;
                mma_tf32(S[n0][0], S[n0][1], S[n0][2], S[n0][3],
                         Qh[ks][0], Qh[ks][1], Qh[ks][2], Qh[ks][3], h0, h1);
                mma_tf32(S[n1][0], S[n1][1], S[n1][2], S[n1][3],
                         Qh[ks][0], Qh[ks][1], Qh[ks][2], Qh[ks][3], h2, h3);
            }
        }

        float rm0 = NEG_INF, rm1 = NEG_INF;
#pragma unroll
        for (int nt = 0; nt < 8; nt++) {
            S[nt][0] = S[nt][0] * 0.125f + mk0[nt].x * (-1e9f);
            S[nt][1] = S[nt][1] * 0.125f + mk0[nt].y * (-1e9f);
            S[nt][2] = S[nt][2] * 0.125f + mk1[nt].x * (-1e9f);
            S[nt][3] = S[nt][3] * 0.125f + mk1[nt].y * (-1e9f);
            rm0 = fmaxf(rm0, fmaxf(S[nt][0], S[nt][1]));
            rm1 = fmaxf(rm1, fmaxf(S[nt][2], S[nt][3]));
        }
        rm0 = fmaxf(rm0, __shfl_xor_sync(0xffffffffu, rm0, 1));
        rm0 = fmaxf(rm0, __shfl_xor_sync(0xffffffffu, rm0, 2));
        rm1 = fmaxf(rm1, __shfl_xor_sync(0xffffffffu, rm1, 1));
        rm1 = fmaxf(rm1, __shfl_xor_sync(0xffffffffu, rm1, 2));

        const float nm0 = fmaxf(m0r, rm0);
        const float nm1 = fmaxf(m1r, rm1);
        const float sc0 = __expf(m0r - nm0);
        const float sc1 = __expf(m1r - nm1);
        m0r = nm0; m1r = nm1;

        float rs0 = 0.f, rs1 = 0.f;
#pragma unroll
        for (int nt = 0; nt < 8; nt++) {
            S[nt][0] = __expf(S[nt][0] - nm0);
            S[nt][1] = __expf(S[nt][1] - nm0);
            S[nt][2] = __expf(S[nt][2] - nm1);
            S[nt][3] = __expf(S[nt][3] - nm1);
            rs0 += S[nt][0] + S[nt][1];
            rs1 += S[nt][2] + S[nt][3];
        }
        rs0 += __shfl_xor_sync(0xffffffffu, rs0, 1);
        rs0 += __shfl_xor_sync(0xffffffffu, rs0, 2);
        rs1 += __shfl_xor_sync(0xffffffffu, rs1, 1);
        rs1 += __shfl_xor_sync(0xffffffffu, rs1, 2);
        l0r = l0r * sc0 + rs0;
        l1r = l1r * sc1 + rs1;

#pragma unroll
        for (int nt = 0; nt < 8; nt++) {
            O[nt][0] *= sc0; O[nt][1] *= sc0;
            O[nt][2] *= sc1; O[nt][3] *= sc1;
        }

        {
            float* p0 = Pbuf + (wm + rq) * FSTR + 2 * cq;
            float* p1 = p0 + 8 * FSTR;
#pragma unroll
            for (int nt = 0; nt < 8; nt++) {
                *(float2*)(p0 + nt * 8) =
                    make_float2(tf32_round(S[nt][0]), tf32_round(S[nt][1]));
                *(float2*)(p1 + nt * 8) =
                    make_float2(tf32_round(S[nt][2]), tf32_round(S[nt][3]));
            }
        }
        __syncwarp();

        const uint32_t pb = sP + (uint32_t)(((wm + row_add) * FSTR + koff) * 4);
        const uint32_t vb = sVt + (uint32_t)((kt & 1) * KV_TILE * 4)
                          + (uint32_t)((row_add * FSTR + koff) * 4);
#pragma unroll
        for (int ks = 0; ks < 8; ks++) {
            uint32_t pr0, pr1, pr2, pr3;
            ldsm_x4(pr0, pr1, pr2, pr3, pb + (uint32_t)(ks * 32));
            uint32_t a0 = pr0, a1 = pr2, a2 = pr1, a3 = pr3;
#pragma unroll
            for (int p = 0; p < 4; p++) {
                uint32_t v0, v1, v2, v3;
                ldsm_x4(v0, v1, v2, v3, vb + (uint32_t)((p * 16 * FSTR) * 4 + ks * 32));
                const int n0 = 2 * p, n1 = 2 * p + 1;
                mma_tf32(O[n0][0], O[n0][1], O[n0][2], O[n0][3], a0, a1, a2, a3, v0, v1);
                mma_tf32(O[n1][0], O[n1][1], O[n1][2], O[n1][3], a0, a1, a2, a3, v2, v3);
            }
        }
    }

    const float inv0 = 1.f / l0r;
    const float inv1 = 1.f / l1r;
    const size_t base_off = ((size_t)b * Ss + q0 + wm + rq) * Dd + h * DP + 2 * cq;
    float* o0 = Out + base_off;
    float* o1 = o0 + (size_t)8 * Dd;
    float* f0 = FCin + base_off;
    float* f1 = f0 + (size_t)8 * Dd;
#pragma unroll
    for (int nt = 0; nt < 8; nt++) {
        float a = O[nt][0] * inv0, bb2 = O[nt][1] * inv0;
        float c = O[nt][2] * inv1, d = O[nt][3] * inv1;
        *(float2*)(o0 + nt * 8) = make_float2(a, bb2);
        *(float2*)(o1 + nt * 8) = make_float2(c, d);
        *(float2*)(f0 + nt * 8) = make_float2(tf32_round(a), tf32_round(bb2));
        *(float2*)(f1 + nt * 8) = make_float2(tf32_round(c), tf32_round(d));
    }
}

// ---------------------------------------------------------------------------
extern "C" void kernel_launch(void* const* d_in, const int* in_sizes, int n_in,
                              void* d_out, int out_size)
{
    const float* q    = (const float*)d_in[0];
    const float* k    = (const float*)d_in[1];
    const float* v    = (const float*)d_in[2];
    const float* mask = (const float*)d_in[3];
    const float* wq_w = (const float*)d_in[4];
    const float* wq_b = (const float*)d_in[5];
    const float* wk_w = (const float*)d_in[6];
    const float* wk_b = (const float*)d_in[7];
    const float* wv_w = (const float*)d_in[8];
    const float* wv_b = (const float*)d_in[9];
    const float* fc_w = (const float*)d_in[10];
    const float* fc_b = (const float*)d_in[11];

    float *pQ, *pKh, *pVT, *pScr, *pFC;
    float *pqr, *pkr, *pvr, *pwqr, *pwkr, *pwvr, *pwfr;
    cudaGetSymbolAddress((void**)&pQ, g_Qp);
    cudaGetSymbolAddress((void**)&pKh, g_Kh);
    cudaGetSymbolAddress((void**)&pVT, g_VT);
    cudaGetSymbolAddress((void**)&pScr, g_attn_scratch);
    cudaGetSymbolAddress((void**)&pFC, g_FCin);
    cudaGetSymbolAddress((void**)&pqr, g_qr);
    cudaGetSymbolAddress((void**)&pkr, g_kr);
    cudaGetSymbolAddress((void**)&pvr, g_vr);
    cudaGetSymbolAddress((void**)&pwqr, g_wqr);
    cudaGetSymbolAddress((void**)&pwkr, g_wkr);
    cudaGetSymbolAddress((void**)&pwvr, g_wvr);
    cudaGetSymbolAddress((void**)&pwfr, g_wfr);

    float* out_main = (float*)d_out;
    const size_t OUT1 = (size_t)MM * Dd;
    float* attn_out = ((size_t)out_size >= 2 * OUT1) ? (out_main + OUT1) : pScr;

    static bool attr_set = false;
    if (!attr_set) {
        cudaFuncSetAttribute(flash_attn_tc, cudaFuncAttributeMaxDynamicSharedMemorySize,
                             FLASH_SMEM_BYTES);
        attr_set = true;
    }

    RoundArgs ra;
    ra.src[0] = (const float4*)q;    ra.dst[0] = (float4*)pqr;
    ra.src[1] = (const float4*)k;    ra.dst[1] = (float4*)pkr;
    ra.src[2] = (const float4*)v;    ra.dst[2] = (float4*)pvr;
    ra.src[3] = (const float4*)wq_w; ra.dst[3] = (float4*)pwqr;
    ra.src[4] = (const float4*)wk_w; ra.dst[4] = (float4*)pwkr;
    ra.src[5] = (const float4*)wv_w; ra.dst[5] = (float4*)pwvr;
    ra.src[6] = (const float4*)fc_w; ra.dst[6] = (float4*)pwfr;
    round_all_kernel<<<(NTOT4 + 255) / 256, 256>>>(ra);

    qkv_gemm<<<dim3(Dd / GBN, MM / GBM, 3), 256>>>(
        pqr, pkr, pvr, pwqr, pwkr, pwvr, wq_b, wk_b, wv_b, pQ, pKh, pVT);

    flash_attn_tc<<<dim3(Ss / 64, Hh, Bb), 128, FLASH_SMEM_BYTES>>>(
        pQ, pKh, pVT, mask, attn_out, pFC);

    fc_gemm<<<dim3(Dd / GBN, MM / GBM), 256>>>(pFC, pwfr, fc_b, out_main);
}

// round 14
// speedup vs baseline: 1.0650x; 1.0494x over previous
#include <cuda_runtime.h>
#include <cstdint>

// ---------------------------------------------------------------------------
// MultiHeadAttn: B=2, S=2048, D=1024, H=16, depth=64
// Stage 0: 7 simple round_tf32 streaming launches (R11-proven).
// Stage 1: merged QKV projections, cvt-free 2-stage pipeline, ONE sync/iter.
// Stage 2: flash attention (unchanged R11): 64q CTA, 4 warps, 2 CTA/SM.
// Stage 3: fc output projection, same single-sync mainloop.
// ---------------------------------------------------------------------------

#define NEG_INF (-3.402823466e38f)

static constexpr int Bb = 2;
static constexpr int Ss = 2048;
static constexpr int Dd = 1024;
static constexpr int Hh = 16;
static constexpr int DP = 64;
static constexpr int MM = Bb * Ss;  // 4096

__device__ float g_Qp[(size_t)MM * Dd];
__device__ float g_Kh[(size_t)MM * Dd];
__device__ float g_VT[(size_t)MM * Dd];   // [B, H, DP, Ss]
__device__ float g_attn_scratch[(size_t)MM * Dd];
__device__ float g_FCin[(size_t)MM * Dd];
__device__ float g_qr[(size_t)MM * Dd];
__device__ float g_kr[(size_t)MM * Dd];
__device__ float g_vr[(size_t)MM * Dd];
__device__ float g_wqr[(size_t)Dd * Dd];
__device__ float g_wkr[(size_t)Dd * Dd];
__device__ float g_wvr[(size_t)Dd * Dd];
__device__ float g_wfr[(size_t)Dd * Dd];

// ---------------------------------------------------------------------------
// PTX helpers
// ---------------------------------------------------------------------------
__device__ __forceinline__ uint32_t cvta_smem(const void* p) {
    return (uint32_t)__cvta_generic_to_shared(p);
}
__device__ __forceinline__ void cp_async16(uint32_t dst, const void* src) {
    asm volatile("cp.async.cg.shared.global [%0], [%1], 16;\n" :: "r"(dst), "l"(src));
}
__device__ __forceinline__ void cp_commit() {
    asm volatile("cp.async.commit_group;\n");
}
__device__ __forceinline__ void cp_wait0() {
    asm volatile("cp.async.wait_group 0;\n");
}
__device__ __forceinline__ void ldsm_x4(uint32_t& r0, uint32_t& r1, uint32_t& r2, uint32_t& r3,
                                        uint32_t addr) {
    asm volatile("ldmatrix.sync.aligned.m8n8.x4.shared.b16 {%0,%1,%2,%3}, [%4];\n"
                 : "=r"(r0), "=r"(r1), "=r"(r2), "=r"(r3) : "r"(addr));
}
__device__ __forceinline__ float tf32_round(float x) {
    uint32_t r;
    asm volatile("cvt.rna.tf32.f32 %0, %1;\n" : "=r"(r) : "f"(x));
    return __uint_as_float(r);
}
__device__ __forceinline__ void mma_tf32(float& d0, float& d1, float& d2, float& d3,
                                         uint32_t a0, uint32_t a1, uint32_t a2, uint32_t a3,
                                         uint32_t b0, uint32_t b1) {
    asm volatile(
        "mma.sync.aligned.m16n8k8.row.col.f32.tf32.tf32.f32 "
        "{%0,%1,%2,%3}, {%4,%5,%6,%7}, {%8,%9}, {%0,%1,%2,%3};\n"
        : "+f"(d0), "+f"(d1), "+f"(d2), "+f"(d3)
        : "r"(a0), "r"(a1), "r"(a2), "r"(a3), "r"(b0), "r"(b1));
}

// ---------------------------------------------------------------------------
// Stage 0: streaming tf32 rounding pass (float4 vectorized, one tensor each).
// ---------------------------------------------------------------------------
__global__ void round_tf32_kernel(const float4* __restrict__ src,
                                  float4* __restrict__ dst, int n4)
{
    int i = blockIdx.x * blockDim.x + threadIdx.x;
    if (i < n4) {
        float4 v = src[i];
        v.x = tf32_round(v.x);
        v.y = tf32_round(v.y);
        v.z = tf32_round(v.z);
        v.w = tf32_round(v.w);
        dst[i] = v;
    }
}

// ---------------------------------------------------------------------------
// GEMM mainloop: 128x128 tile, BK=16, 2-stage, cvt-free, ONE sync per iter.
// Safety: prefetch at iter kt writes stage (kt+1)&1, last read at iter kt-1;
// the top-of-kt sync orders all warps past iter kt-1.
// ---------------------------------------------------------------------------
#define GBM 128
#define GBN 128
#define GBK 16
#define GSTR 20
#define GTILE_BYTES (GBM * GSTR * 4)

struct GemmCtx {
    float acc[4][4][4];
};

__device__ __forceinline__ void gemm_mainloop(
    const float* __restrict__ A, const float* __restrict__ W,
    int m0, int n0, int K, float (*As)[GBM * GSTR], float (*Bs)[GBN * GSTR],
    GemmCtx& ctx)
{
    const int tid  = threadIdx.x;
    const int lane = tid & 31;
    const int wid  = tid >> 5;
    const int wm   = (wid & 1) * 64;
    const int wn   = (wid >> 1) * 32;

    const uint32_t sA = cvta_smem(As);
    const uint32_t sB = cvta_smem(Bs);

    const int lr0 = tid >> 2;
    const int lg  = (tid & 3) * 4;
    const float* Ap0 = A + (size_t)(m0 + lr0) * K + lg;
    const float* Ap1 = A + (size_t)(m0 + lr0 + 64) * K + lg;
    const float* Wp0 = W + (size_t)(n0 + lr0) * K + lg;
    const float* Wp1 = W + (size_t)(n0 + lr0 + 64) * K + lg;
    const uint32_t dA0 = sA + (uint32_t)((lr0 * GSTR + lg) * 4);
    const uint32_t dA1 = sA + (uint32_t)(((lr0 + 64) * GSTR + lg) * 4);
    const uint32_t dB0 = sB + (uint32_t)((lr0 * GSTR + lg) * 4);
    const uint32_t dB1 = sB + (uint32_t)(((lr0 + 64) * GSTR + lg) * 4);

    const int g       = lane >> 3;
    const int glr     = lane & 7;
    const int row_add = ((g >> 1) << 3) + glr;
    const int koff    = (g & 1) << 2;
    const uint32_t aBase = sA + (uint32_t)(((wm + row_add) * GSTR + koff) * 4);
    const uint32_t bBase = sB + (uint32_t)(((wn + row_add) * GSTR + koff) * 4);

#pragma unroll
    for (int i = 0; i < 4; i++)
#pragma unroll
        for (int j = 0; j < 4; j++)
#pragma unroll
            for (int c = 0; c < 4; c++) ctx.acc[i][j][c] = 0.f;

    const int NSTAGE = K / GBK;

    cp_async16(dA0, Ap0); cp_async16(dA1, Ap1);
    cp_async16(dB0, Wp0); cp_async16(dB1, Wp1);
    cp_commit();

    for (int kt = 0; kt < NSTAGE; kt++) {
        cp_wait0();
        __syncthreads();   // tile kt visible; all warps past iter kt-1 reads

        if (kt + 1 < NSTAGE) {
            const int k0 = (kt + 1) * GBK;
            const uint32_t bo = (uint32_t)(((kt + 1) & 1) * GTILE_BYTES);
            cp_async16(dA0 + bo, Ap0 + k0);
            cp_async16(dA1 + bo, Ap1 + k0);
            cp_async16(dB0 + bo, Wp0 + k0);
            cp_async16(dB1 + bo, Wp1 + k0);
            cp_commit();
        }

        const uint32_t bo = (uint32_t)((kt & 1) * GTILE_BYTES);
#pragma unroll
        for (int ks = 0; ks < 2; ks++) {
            const uint32_t ao = aBase + bo + (uint32_t)(ks * 32);
            const uint32_t bb = bBase + bo + (uint32_t)(ks * 32);

            uint32_t af[4][4], bf[4][2];
#pragma unroll
            for (int mt = 0; mt < 4; mt++) {
                uint32_t r0, r1, r2, r3;
                ldsm_x4(r0, r1, r2, r3, ao + (uint32_t)(mt * 16 * GSTR * 4));
                af[mt][0] = r0;
                af[mt][1] = r2;
                af[mt][2] = r1;
                af[mt][3] = r3;
            }
#pragma unroll
            for (int p = 0; p < 2; p++) {
                uint32_t r0, r1, r2, r3;
                ldsm_x4(r0, r1, r2, r3, bb + (uint32_t)(p * 16 * GSTR * 4));
                bf[2 * p][0]     = r0;
                bf[2 * p][1]     = r1;
                bf[2 * p + 1][0] = r2;
                bf[2 * p + 1][1] = r3;
            }
#pragma unroll
            for (int mt = 0; mt < 4; mt++)
#pragma unroll
                for (int nt = 0; nt < 4; nt++)
                    mma_tf32(ctx.acc[mt][nt][0], ctx.acc[mt][nt][1],
                             ctx.acc[mt][nt][2], ctx.acc[mt][nt][3],
                             af[mt][0], af[mt][1], af[mt][2], af[mt][3],
                             bf[nt][0], bf[nt][1]);
        }
        // no bottom sync: next iteration's top sync provides the ordering
    }
}

// ---------------------------------------------------------------------------
// Merged QKV projection. grid.z: 0=Q, 1=K, 2=V^T. All outputs tf32-rounded.
// ---------------------------------------------------------------------------
__global__ __launch_bounds__(256, 2)
void qkv_gemm(const float* __restrict__ q, const float* __restrict__ k,
              const float* __restrict__ v,
              const float* __restrict__ wq, const float* __restrict__ wk,
              const float* __restrict__ wv,
              const float* __restrict__ bq, const float* __restrict__ bk,
              const float* __restrict__ bv,
              float* __restrict__ Qout, float* __restrict__ Kh,
              float* __restrict__ VT)
{
    __shared__ __align__(16) float As[2][GBM * GSTR];
    __shared__ __align__(16) float Bs[2][GBN * GSTR];

    const int z  = blockIdx.z;
    const int m0 = blockIdx.y * GBM;
    const int n0 = blockIdx.x * GBN;

    const float* A    = (z == 0) ? q  : (z == 1) ? k  : v;
    const float* W    = (z == 0) ? wq : (z == 1) ? wk : wv;
    const float* bias = (z == 0) ? bq : (z == 1) ? bk : bv;

    GemmCtx ctx;
    gemm_mainloop(A, W, m0, n0, Dd, As, Bs, ctx);

    const int lane = threadIdx.x & 31;
    const int wid  = threadIdx.x >> 5;
    const int wm   = (wid & 1) * 64;
    const int wn   = (wid >> 1) * 32;

#pragma unroll
    for (int mt = 0; mt < 4; mt++) {
        const int row = m0 + wm + mt * 16 + (lane >> 2);
#pragma unroll
        for (int nt = 0; nt < 4; nt++) {
            const int col = n0 + wn + nt * 8 + (lane & 3) * 2;
            const float b0 = bias[col], b1 = bias[col + 1];
            float v00 = tf32_round(ctx.acc[mt][nt][0] + b0);
            float v01 = tf32_round(ctx.acc[mt][nt][1] + b1);
            float v10 = tf32_round(ctx.acc[mt][nt][2] + b0);
            float v11 = tf32_round(ctx.acc[mt][nt][3] + b1);
            if (z == 0) {
                *(float2*)&Qout[(size_t)row * Dd + col]       = make_float2(v00, v01);
                *(float2*)&Qout[(size_t)(row + 8) * Dd + col] = make_float2(v10, v11);
            } else if (z == 1) {
                *(float2*)&Kh[(size_t)row * Dd + col]       = make_float2(v00, v01);
                *(float2*)&Kh[(size_t)(row + 8) * Dd + col] = make_float2(v10, v11);
            } else {
                const int b_  = row >> 11, s0 = row & 2047;
                const int h_  = col >> 6,  d0 = col & 63;
                float* base = VT + (((size_t)b_ * Hh + h_) * DP + d0) * Ss + s0;
                base[0]      = v00;
                base[Ss]     = v01;
                base[8]      = v10;
                base[Ss + 8] = v11;
            }
        }
    }
}

// fc output projection
__global__ __launch_bounds__(256, 2)
void fc_gemm(const float* __restrict__ A, const float* __restrict__ W,
             const float* __restrict__ bias, float* __restrict__ C)
{
    __shared__ __align__(16) float As[2][GBM * GSTR];
    __shared__ __align__(16) float Bs[2][GBN * GSTR];

    const int m0 = blockIdx.y * GBM;
    const int n0 = blockIdx.x * GBN;

    GemmCtx ctx;
    gemm_mainloop(A, W, m0, n0, Dd, As, Bs, ctx);

    const int lane = threadIdx.x & 31;
    const int wid  = threadIdx.x >> 5;
    const int wm   = (wid & 1) * 64;
    const int wn   = (wid >> 1) * 32;

#pragma unroll
    for (int mt = 0; mt < 4; mt++) {
        const int row = m0 + wm + mt * 16 + (lane >> 2);
#pragma unroll
        for (int nt = 0; nt < 4; nt++) {
            const int col = n0 + wn + nt * 8 + (lane & 3) * 2;
            const float b0 = bias[col], b1 = bias[col + 1];
            *(float2*)&C[(size_t)row * Dd + col] =
                make_float2(ctx.acc[mt][nt][0] + b0, ctx.acc[mt][nt][1] + b1);
            *(float2*)&C[(size_t)(row + 8) * Dd + col] =
                make_float2(ctx.acc[mt][nt][2] + b0, ctx.acc[mt][nt][3] + b1);
        }
    }
}

// ---------------------------------------------------------------------------
// Tensor-core flash attention (unchanged from R11 passing kernel).
// ---------------------------------------------------------------------------
#define FSTR 68
#define KV_TILE (64 * FSTR)
#define FLASH_SMEM_FLOATS (4 * KV_TILE + 64 * FSTR)
#define FLASH_SMEM_BYTES (FLASH_SMEM_FLOATS * 4)   // 87040

__global__ __launch_bounds__(128, 2)
void flash_attn_tc(const float* __restrict__ Qp, const float* __restrict__ Kh_g,
                   const float* __restrict__ VT_g, const float* __restrict__ mask,
                   float* __restrict__ Out, float* __restrict__ FCin)
{
    extern __shared__ float fsm[];
    float* Khb  = fsm;
    float* Vtb  = Khb + 2 * KV_TILE;
    float* Pbuf = Vtb + 2 * KV_TILE;

    const uint32_t sKh = cvta_smem(Khb);
    const uint32_t sVt = cvta_smem(Vtb);
    const uint32_t sP  = cvta_smem(Pbuf);

    const int tid  = threadIdx.x;
    const int lane = tid & 31;
    const int wid  = tid >> 5;
    const int wm   = wid * 16;
    const int q0   = blockIdx.x * 64;
    const int h    = blockIdx.y;
    const int b    = blockIdx.z;

    const float* Qg  = Qp   + ((size_t)b * Ss + q0) * Dd + h * DP;
    const float* Khg = Kh_g + ((size_t)b * Ss) * Dd + h * DP;
    const float* VTg = VT_g + ((size_t)b * Hh + h) * DP * Ss;
    const float* Mg  = mask + (((size_t)b * Hh + h) * Ss + q0) * Ss;

    const int g       = lane >> 3;
    const int glr     = lane & 7;
    const int row_add = ((g >> 1) << 3) + glr;
    const int koff    = (g & 1) << 2;

    const int rq = lane >> 2;
    const int cq = lane & 3;

    const int lrow = tid >> 4;
    const int lcol = tid & 15;

    {
#pragma unroll
        for (int i = 0; i < 8; i++) {
            int row = lrow + 8 * i;
            uint32_t so = (uint32_t)((row * FSTR + lcol * 4) * 4);
            cp_async16(sKh + so, Khg + (size_t)row * Dd + lcol * 4);
            cp_async16(sVt + so, VTg + (size_t)row * Ss + lcol * 4);
        }
        cp_commit();
    }

#pragma unroll
    for (int i = 0; i < 8; i++) {
        int id = tid + 128 * i;
        int row = id >> 4, col = id & 15;
        float4 v = *(const float4*)(Qg + (size_t)row * Dd + col * 4);
        *(float4*)&Pbuf[row * FSTR + col * 4] = v;
    }
    __syncthreads();

    uint32_t Qh[8][4];
    {
        const uint32_t base = sP + (uint32_t)(((wm + row_add) * FSTR + koff) * 4);
#pragma unroll
        for (int ks = 0; ks < 8; ks++) {
            uint32_t r0, r1, r2, r3;
            ldsm_x4(r0, r1, r2, r3, base + (uint32_t)(ks * 32));
            Qh[ks][0] = r0;
            Qh[ks][1] = r2;
            Qh[ks][2] = r1;
            Qh[ks][3] = r3;
        }
    }

    float O[8][4];
#pragma unroll
    for (int nt = 0; nt < 8; nt++)
#pragma unroll
        for (int c = 0; c < 4; c++) O[nt][c] = 0.f;
    float m0r = NEG_INF, m1r = NEG_INF, l0r = 0.f, l1r = 0.f;

    for (int kt = 0; kt < 32; kt++) {
        cp_wait0();
        __syncthreads();

        if (kt + 1 < 32) {
            const uint32_t bo = (uint32_t)(((kt + 1) & 1) * KV_TILE * 4);
            const float* khg = Khg + (size_t)(kt + 1) * 64 * Dd;
            const float* vtg = VTg + (size_t)(kt + 1) * 64;
#pragma unroll
            for (int i = 0; i < 8; i++) {
                int row = lrow + 8 * i;
                uint32_t so = (uint32_t)((row * FSTR + lcol * 4) * 4);
                cp_async16(sKh + bo + so, khg + (size_t)row * Dd + lcol * 4);
                cp_async16(sVt + bo + so, vtg + (size_t)row * Ss + lcol * 4);
            }
            cp_commit();
        }

        float2 mk0[8], mk1[8];
        {
            const float* mr0 = Mg + (size_t)(wm + rq) * Ss + kt * 64 + 2 * cq;
            const float* mr1 = mr0 + 8 * Ss;
#pragma unroll
            for (int nt = 0; nt < 8; nt++) {
                mk0[nt] = *(const float2*)(mr0 + nt * 8);
                mk1[nt] = *(const float2*)(mr1 + nt * 8);
            }
        }

        float S[8][4];
#pragma unroll
        for (int nt = 0; nt < 8; nt++)
#pragma unroll
            for (int c = 0; c < 4; c++) S[nt][c] = 0.f;

        const uint32_t khb = sKh + (uint32_t)((kt & 1) * KV_TILE * 4)
                           + (uint32_t)((row_add * FSTR + koff) * 4);
#pragma unroll
        for (int ks = 0; ks < 8; ks++) {
#pragma unroll
            for (int p = 0; p < 4; p++) {
                const uint32_t off = (uint32_t)((p * 16 * FSTR) * 4 + ks * 32);
                uint32_t h0, h1, h2, h3;
                ldsm_x4(h0, h1, h2, h3, khb + off);
                const int n0 = 2 * p, n1 = 2 * p + 1;
                mma_tf32(S[n0][0], S[n0][1], S[n0][2], S[n0][3],
                         Qh[ks][0], Qh[ks][1], Qh[ks][2], Qh[ks][3], h0, h1);
                mma_tf32(S[n1][0], S[n1][1], S[n1][2], S[n1][3],
                         Qh[ks][0], Qh[ks][1], Qh[ks][2], Qh[ks][3], h2, h3);
            }
        }

        float rm0 = NEG_INF, rm1 = NEG_INF;
#pragma unroll
        for (int nt = 0; nt < 8; nt++) {
            S[nt][0] = S[nt][0] * 0.125f + mk0[nt].x * (-1e9f);
            S[nt][1] = S[nt][1] * 0.125f + mk0[nt].y * (-1e9f);
            S[nt][2] = S[nt][2] * 0.125f + mk1[nt].x * (-1e9f);
            S[nt][3] = S[nt][3] * 0.125f + mk1[nt].y * (-1e9f);
            rm0 = fmaxf(rm0, fmaxf(S[nt][0], S[nt][1]));
            rm1 = fmaxf(rm1, fmaxf(S[nt][2], S[nt][3]));
        }
        rm0 = fmaxf(rm0, __shfl_xor_sync(0xffffffffu, rm0, 1));
        rm0 = fmaxf(rm0, __shfl_xor_sync(0xffffffffu, rm0, 2));
        rm1 = fmaxf(rm1, __shfl_xor_sync(0xffffffffu, rm1, 1));
        rm1 = fmaxf(rm1, __shfl_xor_sync(0xffffffffu, rm1, 2));

        const float nm0 = fmaxf(m0r, rm0);
        const float nm1 = fmaxf(m1r, rm1);
        const float sc0 = __expf(m0r - nm0);
        const float sc1 = __expf(m1r - nm1);
        m0r = nm0; m1r = nm1;

        float rs0 = 0.f, rs1 = 0.f;
#pragma unroll
        for (int nt = 0; nt < 8; nt++) {
            S[nt][0] = __expf(S[nt][0] - nm0);
            S[nt][1] = __expf(S[nt][1] - nm0);
            S[nt][2] = __expf(S[nt][2] - nm1);
            S[nt][3] = __expf(S[nt][3] - nm1);
            rs0 += S[nt][0] + S[nt][1];
            rs1 += S[nt][2] + S[nt][3];
        }
        rs0 += __shfl_xor_sync(0xffffffffu, rs0, 1);
        rs0 += __shfl_xor_sync(0xffffffffu, rs0, 2);
        rs1 += __shfl_xor_sync(0xffffffffu, rs1, 1);
        rs1 += __shfl_xor_sync(0xffffffffu, rs1, 2);
        l0r = l0r * sc0 + rs0;
        l1r = l1r * sc1 + rs1;

#pragma unroll
        for (int nt = 0; nt < 8; nt++) {
            O[nt][0] *= sc0; O[nt][1] *= sc0;
            O[nt][2] *= sc1; O[nt][3] *= sc1;
        }

        {
            float* p0 = Pbuf + (wm + rq) * FSTR + 2 * cq;
            float* p1 = p0 + 8 * FSTR;
#pragma unroll
            for (int nt = 0; nt < 8; nt++) {
                *(float2*)(p0 + nt * 8) =
                    make_float2(tf32_round(S[nt][0]), tf32_round(S[nt][1]));
                *(float2*)(p1 + nt * 8) =
                    make_float2(tf32_round(S[nt][2]), tf32_round(S[nt][3]));
            }
        }
        __syncwarp();

        const uint32_t pb = sP + (uint32_t)(((wm + row_add) * FSTR + koff) * 4);
        const uint32_t vb = sVt + (uint32_t)((kt & 1) * KV_TILE * 4)
                          + (uint32_t)((row_add * FSTR + koff) * 4);
#pragma unroll
        for (int ks = 0; ks < 8; ks++) {
            uint32_t pr0, pr1, pr2, pr3;
            ldsm_x4(pr0, pr1, pr2, pr3, pb + (uint32_t)(ks * 32));
            uint32_t a0 = pr0, a1 = pr2, a2 = pr1, a3 = pr3;
#pragma unroll
            for (int p = 0; p < 4; p++) {
                uint32_t v0, v1, v2, v3;
                ldsm_x4(v0, v1, v2, v3, vb + (uint32_t)((p * 16 * FSTR) * 4 + ks * 32));
                const int n0 = 2 * p, n1 = 2 * p + 1;
                mma_tf32(O[n0][0], O[n0][1], O[n0][2], O[n0][3], a0, a1, a2, a3, v0, v1);
                mma_tf32(O[n1][0], O[n1][1], O[n1][2], O[n1][3], a0, a1, a2, a3, v2, v3);
            }
        }
    }

    const float inv0 = 1.f / l0r;
    const float inv1 = 1.f / l1r;
    const size_t base_off = ((size_t)b * Ss + q0 + wm + rq) * Dd + h * DP + 2 * cq;
    float* o0 = Out + base_off;
    float* o1 = o0 + (size_t)8 * Dd;
    float* f0 = FCin + base_off;
    float* f1 = f0 + (size_t)8 * Dd;
#pragma unroll
    for (int nt = 0; nt < 8; nt++) {
        float a = O[nt][0] * inv0, bb2 = O[nt][1] * inv0;
        float c = O[nt][2] * inv1, d = O[nt][3] * inv1;
        *(float2*)(o0 + nt * 8) = make_float2(a, bb2);
        *(float2*)(o1 + nt * 8) = make_float2(c, d);
        *(float2*)(f0 + nt * 8) = make_float2(tf32_round(a), tf32_round(bb2));
        *(float2*)(f1 + nt * 8) = make_float2(tf32_round(c), tf32_round(d));
    }
}

// ---------------------------------------------------------------------------
extern "C" void kernel_launch(void* const* d_in, const int* in_sizes, int n_in,
                              void* d_out, int out_size)
{
    const float* q    = (const float*)d_in[0];
    const float* k    = (const float*)d_in[1];
    const float* v    = (const float*)d_in[2];
    const float* mask = (const float*)d_in[3];
    const float* wq_w = (const float*)d_in[4];
    const float* wq_b = (const float*)d_in[5];
    const float* wk_w = (const float*)d_in[6];
    const float* wk_b = (const float*)d_in[7];
    const float* wv_w = (const float*)d_in[8];
    const float* wv_b = (const float*)d_in[9];
    const float* fc_w = (const float*)d_in[10];
    const float* fc_b = (const float*)d_in[11];

    float *pQ, *pKh, *pVT, *pScr, *pFC;
    float *pqr, *pkr, *pvr, *pwqr, *pwkr, *pwvr, *pwfr;
    cudaGetSymbolAddress((void**)&pQ, g_Qp);
    cudaGetSymbolAddress((void**)&pKh, g_Kh);
    cudaGetSymbolAddress((void**)&pVT, g_VT);
    cudaGetSymbolAddress((void**)&pScr, g_attn_scratch);
    cudaGetSymbolAddress((void**)&pFC, g_FCin);
    cudaGetSymbolAddress((void**)&pqr, g_qr);
    cudaGetSymbolAddress((void**)&pkr, g_kr);
    cudaGetSymbolAddress((void**)&pvr, g_vr);
    cudaGetSymbolAddress((void**)&pwqr, g_wqr);
    cudaGetSymbolAddress((void**)&pwkr, g_wkr);
    cudaGetSymbolAddress((void**)&pwvr, g_wvr);
    cudaGetSymbolAddress((void**)&pwfr, g_wfr);

    float* out_main = (float*)d_out;
    const size_t OUT1 = (size_t)MM * Dd;
    float* attn_out = ((size_t)out_size >= 2 * OUT1) ? (out_main + OUT1) : pScr;

    static bool attr_set = false;
    if (!attr_set) {
        cudaFuncSetAttribute(flash_attn_tc, cudaFuncAttributeMaxDynamicSharedMemorySize,
                             FLASH_SMEM_BYTES);
        attr_set = true;
    }

    // Stage 0: tf32 rounding pre-pass (7 simple streaming launches)
    const int NA4 = (MM * Dd) / 4;       // 1M float4
    const int NW4 = (Dd * Dd) / 4;       // 256K float4
    round_tf32_kernel<<<(NA4 + 255) / 256, 256>>>((const float4*)q, (float4*)pqr, NA4);
    round_tf32_kernel<<<(NA4 + 255) / 256, 256>>>((const float4*)k, (float4*)pkr, NA4);
    round_tf32_kernel<<<(NA4 + 255) / 256, 256>>>((const float4*)v, (float4*)pvr, NA4);
    round_tf32_kernel<<<(NW4 + 255) / 256, 256>>>((const float4*)wq_w, (float4*)pwqr, NW4);
    round_tf32_kernel<<<(NW4 + 255) / 256, 256>>>((const float4*)wk_w, (float4*)pwkr, NW4);
    round_tf32_kernel<<<(NW4 + 255) / 256, 256>>>((const float4*)wv_w, (float4*)pwvr, NW4);
    round_tf32_kernel<<<(NW4 + 255) / 256, 256>>>((const float4*)fc_w, (float4*)pwfr, NW4);

    qkv_gemm<<<dim3(Dd / GBN, MM / GBM, 3), 256>>>(
        pqr, pkr, pvr, pwqr, pwkr, pwvr, wq_b, wk_b, wv_b, pQ, pKh, pVT);

    flash_attn_tc<<<dim3(Ss / 64, Hh, Bb), 128, FLASH_SMEM_BYTES>>>(
        pQ, pKh, pVT, mask, attn_out, pFC);

    fc_gemm<<<dim3(Dd / GBN, MM / GBM), 256>>>(pFC, pwfr, fc_b, out_main);
}

// round 15
// speedup vs baseline: 1.0946x; 1.0277x over previous
#include <cuda_runtime.h>
#include <cstdint>

// ---------------------------------------------------------------------------
// MultiHeadAttn: B=2, S=2048, D=1024, H=16, depth=64
// Stage 0: 7 simple round_tf32 streaming launches.
// Stage 1: merged QKV projections, cvt-free 2-stage pipeline, ONE sync/iter.
// Stage 2: flash attention: 128q CTA, 4 warps x 32 q-rows (two m16 tiles),
//          2 CTA/SM. K/V ldsm amortized over 2 m-tiles (smem BW 0.55x).
// Stage 3: fc output projection, same single-sync mainloop.
// ---------------------------------------------------------------------------

#define NEG_INF (-3.402823466e38f)

static constexpr int Bb = 2;
static constexpr int Ss = 2048;
static constexpr int Dd = 1024;
static constexpr int Hh = 16;
static constexpr int DP = 64;
static constexpr int MM = Bb * Ss;  // 4096

__device__ float g_Qp[(size_t)MM * Dd];
__device__ float g_Kh[(size_t)MM * Dd];
__device__ float g_VT[(size_t)MM * Dd];   // [B, H, DP, Ss]
__device__ float g_attn_scratch[(size_t)MM * Dd];
__device__ float g_FCin[(size_t)MM * Dd];
__device__ float g_qr[(size_t)MM * Dd];
__device__ float g_kr[(size_t)MM * Dd];
__device__ float g_vr[(size_t)MM * Dd];
__device__ float g_wqr[(size_t)Dd * Dd];
__device__ float g_wkr[(size_t)Dd * Dd];
__device__ float g_wvr[(size_t)Dd * Dd];
__device__ float g_wfr[(size_t)Dd * Dd];

// ---------------------------------------------------------------------------
// PTX helpers
// ---------------------------------------------------------------------------
__device__ __forceinline__ uint32_t cvta_smem(const void* p) {
    return (uint32_t)__cvta_generic_to_shared(p);
}
__device__ __forceinline__ void cp_async16(uint32_t dst, const void* src) {
    asm volatile("cp.async.cg.shared.global [%0], [%1], 16;\n" :: "r"(dst), "l"(src));
}
__device__ __forceinline__ void cp_commit() {
    asm volatile("cp.async.commit_group;\n");
}
__device__ __forceinline__ void cp_wait0() {
    asm volatile("cp.async.wait_group 0;\n");
}
__device__ __forceinline__ void ldsm_x4(uint32_t& r0, uint32_t& r1, uint32_t& r2, uint32_t& r3,
                                        uint32_t addr) {
    asm volatile("ldmatrix.sync.aligned.m8n8.x4.shared.b16 {%0,%1,%2,%3}, [%4];\n"
                 : "=r"(r0), "=r"(r1), "=r"(r2), "=r"(r3) : "r"(addr));
}
__device__ __forceinline__ float tf32_round(float x) {
    uint32_t r;
    asm volatile("cvt.rna.tf32.f32 %0, %1;\n" : "=r"(r) : "f"(x));
    return __uint_as_float(r);
}
__device__ __forceinline__ void mma_tf32(float& d0, float& d1, float& d2, float& d3,
                                         uint32_t a0, uint32_t a1, uint32_t a2, uint32_t a3,
                                         uint32_t b0, uint32_t b1) {
    asm volatile(
        "mma.sync.aligned.m16n8k8.row.col.f32.tf32.tf32.f32 "
        "{%0,%1,%2,%3}, {%4,%5,%6,%7}, {%8,%9}, {%0,%1,%2,%3};\n"
        : "+f"(d0), "+f"(d1), "+f"(d2), "+f"(d3)
        : "r"(a0), "r"(a1), "r"(a2), "r"(a3), "r"(b0), "r"(b1));
}

// ---------------------------------------------------------------------------
// Stage 0: streaming tf32 rounding pass (float4 vectorized, one tensor each).
// ---------------------------------------------------------------------------
__global__ void round_tf32_kernel(const float4* __restrict__ src,
                                  float4* __restrict__ dst, int n4)
{
    int i = blockIdx.x * blockDim.x + threadIdx.x;
    if (i < n4) {
        float4 v = src[i];
        v.x = tf32_round(v.x);
        v.y = tf32_round(v.y);
        v.z = tf32_round(v.z);
        v.w = tf32_round(v.w);
        dst[i] = v;
    }
}

// ---------------------------------------------------------------------------
// GEMM mainloop: 128x128 tile, BK=16, 2-stage, cvt-free, ONE sync per iter.
// ---------------------------------------------------------------------------
#define GBM 128
#define GBN 128
#define GBK 16
#define GSTR 20
#define GTILE_BYTES (GBM * GSTR * 4)

struct GemmCtx {
    float acc[4][4][4];
};

__device__ __forceinline__ void gemm_mainloop(
    const float* __restrict__ A, const float* __restrict__ W,
    int m0, int n0, int K, float (*As)[GBM * GSTR], float (*Bs)[GBN * GSTR],
    GemmCtx& ctx)
{
    const int tid  = threadIdx.x;
    const int lane = tid & 31;
    const int wid  = tid >> 5;
    const int wm   = (wid & 1) * 64;
    const int wn   = (wid >> 1) * 32;

    const uint32_t sA = cvta_smem(As);
    const uint32_t sB = cvta_smem(Bs);

    const int lr0 = tid >> 2;
    const int lg  = (tid & 3) * 4;
    const float* Ap0 = A + (size_t)(m0 + lr0) * K + lg;
    const float* Ap1 = A + (size_t)(m0 + lr0 + 64) * K + lg;
    const float* Wp0 = W + (size_t)(n0 + lr0) * K + lg;
    const float* Wp1 = W + (size_t)(n0 + lr0 + 64) * K + lg;
    const uint32_t dA0 = sA + (uint32_t)((lr0 * GSTR + lg) * 4);
    const uint32_t dA1 = sA + (uint32_t)(((lr0 + 64) * GSTR + lg) * 4);
    const uint32_t dB0 = sB + (uint32_t)((lr0 * GSTR + lg) * 4);
    const uint32_t dB1 = sB + (uint32_t)(((lr0 + 64) * GSTR + lg) * 4);

    const int g       = lane >> 3;
    const int glr     = lane & 7;
    const int row_add = ((g >> 1) << 3) + glr;
    const int koff    = (g & 1) << 2;
    const uint32_t aBase = sA + (uint32_t)(((wm + row_add) * GSTR + koff) * 4);
    const uint32_t bBase = sB + (uint32_t)(((wn + row_add) * GSTR + koff) * 4);

#pragma unroll
    for (int i = 0; i < 4; i++)
#pragma unroll
        for (int j = 0; j < 4; j++)
#pragma unroll
            for (int c = 0; c < 4; c++) ctx.acc[i][j][c] = 0.f;

    const int NSTAGE = K / GBK;

    cp_async16(dA0, Ap0); cp_async16(dA1, Ap1);
    cp_async16(dB0, Wp0); cp_async16(dB1, Wp1);
    cp_commit();

    for (int kt = 0; kt < NSTAGE; kt++) {
        cp_wait0();
        __syncthreads();   // tile kt visible; all warps past iter kt-1 reads

        if (kt + 1 < NSTAGE) {
            const int k0 = (kt + 1) * GBK;
            const uint32_t bo = (uint32_t)(((kt + 1) & 1) * GTILE_BYTES);
            cp_async16(dA0 + bo, Ap0 + k0);
            cp_async16(dA1 + bo, Ap1 + k0);
            cp_async16(dB0 + bo, Wp0 + k0);
            cp_async16(dB1 + bo, Wp1 + k0);
            cp_commit();
        }

        const uint32_t bo = (uint32_t)((kt & 1) * GTILE_BYTES);
#pragma unroll
        for (int ks = 0; ks < 2; ks++) {
            const uint32_t ao = aBase + bo + (uint32_t)(ks * 32);
            const uint32_t bb = bBase + bo + (uint32_t)(ks * 32);

            uint32_t af[4][4], bf[4][2];
#pragma unroll
            for (int mt = 0; mt < 4; mt++) {
                uint32_t r0, r1, r2, r3;
                ldsm_x4(r0, r1, r2, r3, ao + (uint32_t)(mt * 16 * GSTR * 4));
                af[mt][0] = r0;
                af[mt][1] = r2;
                af[mt][2] = r1;
                af[mt][3] = r3;
            }
#pragma unroll
            for (int p = 0; p < 2; p++) {
                uint32_t r0, r1, r2, r3;
                ldsm_x4(r0, r1, r2, r3, bb + (uint32_t)(p * 16 * GSTR * 4));
                bf[2 * p][0]     = r0;
                bf[2 * p][1]     = r1;
                bf[2 * p + 1][0] = r2;
                bf[2 * p + 1][1] = r3;
            }
#pragma unroll
            for (int mt = 0; mt < 4; mt++)
#pragma unroll
                for (int nt = 0; nt < 4; nt++)
                    mma_tf32(ctx.acc[mt][nt][0], ctx.acc[mt][nt][1],
                             ctx.acc[mt][nt][2], ctx.acc[mt][nt][3],
                             af[mt][0], af[mt][1], af[mt][2], af[mt][3],
                             bf[nt][0], bf[nt][1]);
        }
    }
}

// ---------------------------------------------------------------------------
// Merged QKV projection. grid.z: 0=Q, 1=K, 2=V^T. All outputs tf32-rounded.
// ---------------------------------------------------------------------------
__global__ __launch_bounds__(256, 2)
void qkv_gemm(const float* __restrict__ q, const float* __restrict__ k,
              const float* __restrict__ v,
              const float* __restrict__ wq, const float* __restrict__ wk,
              const float* __restrict__ wv,
              const float* __restrict__ bq, const float* __restrict__ bk,
              const float* __restrict__ bv,
              float* __restrict__ Qout, float* __restrict__ Kh,
              float* __restrict__ VT)
{
    __shared__ __align__(16) float As[2][GBM * GSTR];
    __shared__ __align__(16) float Bs[2][GBN * GSTR];

    const int z  = blockIdx.z;
    const int m0 = blockIdx.y * GBM;
    const int n0 = blockIdx.x * GBN;

    const float* A    = (z == 0) ? q  : (z == 1) ? k  : v;
    const float* W    = (z == 0) ? wq : (z == 1) ? wk : wv;
    const float* bias = (z == 0) ? bq : (z == 1) ? bk : bv;

    GemmCtx ctx;
    gemm_mainloop(A, W, m0, n0, Dd, As, Bs, ctx);

    const int lane = threadIdx.x & 31;
    const int wid  = threadIdx.x >> 5;
    const int wm   = (wid & 1) * 64;
    const int wn   = (wid >> 1) * 32;

#pragma unroll
    for (int mt = 0; mt < 4; mt++) {
        const int row = m0 + wm + mt * 16 + (lane >> 2);
#pragma unroll
        for (int nt = 0; nt < 4; nt++) {
            const int col = n0 + wn + nt * 8 + (lane & 3) * 2;
            const float b0 = bias[col], b1 = bias[col + 1];
            float v00 = tf32_round(ctx.acc[mt][nt][0] + b0);
            float v01 = tf32_round(ctx.acc[mt][nt][1] + b1);
            float v10 = tf32_round(ctx.acc[mt][nt][2] + b0);
            float v11 = tf32_round(ctx.acc[mt][nt][3] + b1);
            if (z == 0) {
                *(float2*)&Qout[(size_t)row * Dd + col]       = make_float2(v00, v01);
                *(float2*)&Qout[(size_t)(row + 8) * Dd + col] = make_float2(v10, v11);
            } else if (z == 1) {
                *(float2*)&Kh[(size_t)row * Dd + col]       = make_float2(v00, v01);
                *(float2*)&Kh[(size_t)(row + 8) * Dd + col] = make_float2(v10, v11);
            } else {
                const int b_  = row >> 11, s0 = row & 2047;
                const int h_  = col >> 6,  d0 = col & 63;
                float* base = VT + (((size_t)b_ * Hh + h_) * DP + d0) * Ss + s0;
                base[0]      = v00;
                base[Ss]     = v01;
                base[8]      = v10;
                base[Ss + 8] = v11;
            }
        }
    }
}

// fc output projection
__global__ __launch_bounds__(256, 2)
void fc_gemm(const float* __restrict__ A, const float* __restrict__ W,
             const float* __restrict__ bias, float* __restrict__ C)
{
    __shared__ __align__(16) float As[2][GBM * GSTR];
    __shared__ __align__(16) float Bs[2][GBN * GSTR];

    const int m0 = blockIdx.y * GBM;
    const int n0 = blockIdx.x * GBN;

    GemmCtx ctx;
    gemm_mainloop(A, W, m0, n0, Dd, As, Bs, ctx);

    const int lane = threadIdx.x & 31;
    const int wid  = threadIdx.x >> 5;
    const int wm   = (wid & 1) * 64;
    const int wn   = (wid >> 1) * 32;

#pragma unroll
    for (int mt = 0; mt < 4; mt++) {
        const int row = m0 + wm + mt * 16 + (lane >> 2);
#pragma unroll
        for (int nt = 0; nt < 4; nt++) {
            const int col = n0 + wn + nt * 8 + (lane & 3) * 2;
            const float b0 = bias[col], b1 = bias[col + 1];
            *(float2*)&C[(size_t)row * Dd + col] =
                make_float2(ctx.acc[mt][nt][0] + b0, ctx.acc[mt][nt][1] + b1);
            *(float2*)&C[(size_t)(row + 8) * Dd + col] =
                make_float2(ctx.acc[mt][nt][2] + b0, ctx.acc[mt][nt][3] + b1);
        }
    }
}

// ---------------------------------------------------------------------------
// Tensor-core flash attention. 128-query CTA, 4 warps x 32 q rows (2 m-tiles),
// 2 CTA/SM. K/V ldsm fragments reused across both m-tiles.
// ---------------------------------------------------------------------------
#define FSTR 68
#define KV_TILE (64 * FSTR)
#define FLASH_SMEM_FLOATS (4 * KV_TILE + 128 * FSTR)
#define FLASH_SMEM_BYTES (FLASH_SMEM_FLOATS * 4)   // 104448

__global__ __launch_bounds__(128, 2)
void flash_attn_tc(const float* __restrict__ Qp, const float* __restrict__ Kh_g,
                   const float* __restrict__ VT_g, const float* __restrict__ mask,
                   float* __restrict__ Out, float* __restrict__ FCin)
{
    extern __shared__ float fsm[];
    float* Khb  = fsm;                        // 2 * KV_TILE
    float* Vtb  = Khb + 2 * KV_TILE;          // 2 * KV_TILE
    float* Pbuf = Vtb + 2 * KV_TILE;          // 128 * FSTR (Q stage, then P)

    const uint32_t sKh = cvta_smem(Khb);
    const uint32_t sVt = cvta_smem(Vtb);
    const uint32_t sP  = cvta_smem(Pbuf);

    const int tid  = threadIdx.x;
    const int lane = tid & 31;
    const int wid  = tid >> 5;          // 0..3
    const int wm   = wid * 32;          // warp's first q row (32 rows per warp)
    const int q0   = blockIdx.x * 128;
    const int h    = blockIdx.y;
    const int b    = blockIdx.z;

    const float* Qg  = Qp   + ((size_t)b * Ss + q0) * Dd + h * DP;
    const float* Khg = Kh_g + ((size_t)b * Ss) * Dd + h * DP;
    const float* VTg = VT_g + ((size_t)b * Hh + h) * DP * Ss;
    const float* Mg  = mask + (((size_t)b * Hh + h) * Ss + q0) * Ss;

    const int g       = lane >> 3;
    const int glr     = lane & 7;
    const int row_add = ((g >> 1) << 3) + glr;
    const int koff    = (g & 1) << 2;

    const int rq = lane >> 2;
    const int cq = lane & 3;

    const int lrow = tid >> 4;          // 0..7 (+8*i)
    const int lcol = tid & 15;

    // ---- prefetch K/V tile 0 ----
    {
#pragma unroll
        for (int i = 0; i < 8; i++) {
            int row = lrow + 8 * i;
            uint32_t so = (uint32_t)((row * FSTR + lcol * 4) * 4);
            cp_async16(sKh + so, Khg + (size_t)row * Dd + lcol * 4);
            cp_async16(sVt + so, VTg + (size_t)row * Ss + lcol * 4);
        }
        cp_commit();
    }

    // ---- stage Q (128 rows) into Pbuf ----
#pragma unroll
    for (int i = 0; i < 16; i++) {
        int id = tid + 128 * i;              // 0..2047
        int row = id >> 4, col = id & 15;    // 128 rows x 16 chunks
        float4 v = *(const float4*)(Qg + (size_t)row * Dd + col * 4);
        *(float4*)&Pbuf[row * FSTR + col * 4] = v;
    }
    __syncthreads();

    // ---- extract Q fragments: two m16 tiles per warp ----
    uint32_t Qh[2][8][4];
#pragma unroll
    for (int mt = 0; mt < 2; mt++) {
        const uint32_t base = sP + (uint32_t)(((wm + mt * 16 + row_add) * FSTR + koff) * 4);
#pragma unroll
        for (int ks = 0; ks < 8; ks++) {
            uint32_t r0, r1, r2, r3;
            ldsm_x4(r0, r1, r2, r3, base + (uint32_t)(ks * 32));
            Qh[mt][ks][0] = r0;
            Qh[mt][ks][1] = r2;
            Qh[mt][ks][2] = r1;
            Qh[mt][ks][3] = r3;
        }
    }

    float O[2][8][4];
#pragma unroll
    for (int mt = 0; mt < 2; mt++)
#pragma unroll
        for (int nt = 0; nt < 8; nt++)
#pragma unroll
            for (int c = 0; c < 4; c++) O[mt][nt][c] = 0.f;
    float m0r[2] = {NEG_INF, NEG_INF}, m1r[2] = {NEG_INF, NEG_INF};
    float l0r[2] = {0.f, 0.f}, l1r[2] = {0.f, 0.f};

    for (int kt = 0; kt < 32; kt++) {
        cp_wait0();
        __syncthreads();   // tile kt visible; all warps done with buffer (kt+1)&1

        // prefetch tile kt+1
        if (kt + 1 < 32) {
            const uint32_t bo = (uint32_t)(((kt + 1) & 1) * KV_TILE * 4);
            const float* khg = Khg + (size_t)(kt + 1) * 64 * Dd;
            const float* vtg = VTg + (size_t)(kt + 1) * 64;
#pragma unroll
            for (int i = 0; i < 8; i++) {
                int row = lrow + 8 * i;
                uint32_t so = (uint32_t)((row * FSTR + lcol * 4) * 4);
                cp_async16(sKh + bo + so, khg + (size_t)row * Dd + lcol * 4);
                cp_async16(sVt + bo + so, vtg + (size_t)row * Ss + lcol * 4);
            }
            cp_commit();
        }

        // ---- S = Qhat · Khat for both m-tiles (K frags shared) ----
        float S[2][8][4];
#pragma unroll
        for (int mt = 0; mt < 2; mt++)
#pragma unroll
            for (int nt = 0; nt < 8; nt++)
#pragma unroll
                for (int c = 0; c < 4; c++) S[mt][nt][c] = 0.f;

        const uint32_t khb = sKh + (uint32_t)((kt & 1) * KV_TILE * 4)
                           + (uint32_t)((row_add * FSTR + koff) * 4);
#pragma unroll
        for (int ks = 0; ks < 8; ks++) {
#pragma unroll
            for (int p = 0; p < 4; p++) {
                const uint32_t off = (uint32_t)((p * 16 * FSTR) * 4 + ks * 32);
                uint32_t h0, h1, h2, h3;
                ldsm_x4(h0, h1, h2, h3, khb + off);
                const int n0 = 2 * p, n1 = 2 * p + 1;
#pragma unroll
                for (int mt = 0; mt < 2; mt++) {
                    mma_tf32(S[mt][n0][0], S[mt][n0][1], S[mt][n0][2], S[mt][n0][3],
                             Qh[mt][ks][0], Qh[mt][ks][1], Qh[mt][ks][2], Qh[mt][ks][3],
                             h0, h1);
                    mma_tf32(S[mt][n1][0], S[mt][n1][1], S[mt][n1][2], S[mt][n1][3],
                             Qh[mt][ks][0], Qh[mt][ks][1], Qh[mt][ks][2], Qh[mt][ks][3],
                             h2, h3);
                }
            }
        }

        // ---- per m-tile: mask + scale + online softmax + P store ----
#pragma unroll
        for (int mt = 0; mt < 2; mt++) {
            float2 mk0[8], mk1[8];
            {
                const float* mr0 = Mg + (size_t)(wm + mt * 16 + rq) * Ss + kt * 64 + 2 * cq;
                const float* mr1 = mr0 + 8 * Ss;
#pragma unroll
                for (int nt = 0; nt < 8; nt++) {
                    mk0[nt] = *(const float2*)(mr0 + nt * 8);
                    mk1[nt] = *(const float2*)(mr1 + nt * 8);
                }
            }

            float rm0 = NEG_INF, rm1 = NEG_INF;
#pragma unroll
            for (int nt = 0; nt < 8; nt++) {
                S[mt][nt][0] = S[mt][nt][0] * 0.125f + mk0[nt].x * (-1e9f);
                S[mt][nt][1] = S[mt][nt][1] * 0.125f + mk0[nt].y * (-1e9f);
                S[mt][nt][2] = S[mt][nt][2] * 0.125f + mk1[nt].x * (-1e9f);
                S[mt][nt][3] = S[mt][nt][3] * 0.125f + mk1[nt].y * (-1e9f);
                rm0 = fmaxf(rm0, fmaxf(S[mt][nt][0], S[mt][nt][1]));
                rm1 = fmaxf(rm1, fmaxf(S[mt][nt][2], S[mt][nt][3]));
            }
            rm0 = fmaxf(rm0, __shfl_xor_sync(0xffffffffu, rm0, 1));
            rm0 = fmaxf(rm0, __shfl_xor_sync(0xffffffffu, rm0, 2));
            rm1 = fmaxf(rm1, __shfl_xor_sync(0xffffffffu, rm1, 1));
            rm1 = fmaxf(rm1, __shfl_xor_sync(0xffffffffu, rm1, 2));

            const float nm0 = fmaxf(m0r[mt], rm0);
            const float nm1 = fmaxf(m1r[mt], rm1);
            const float sc0 = __expf(m0r[mt] - nm0);
            const float sc1 = __expf(m1r[mt] - nm1);
            m0r[mt] = nm0; m1r[mt] = nm1;

            float rs0 = 0.f, rs1 = 0.f;
#pragma unroll
            for (int nt = 0; nt < 8; nt++) {
                S[mt][nt][0] = __expf(S[mt][nt][0] - nm0);
                S[mt][nt][1] = __expf(S[mt][nt][1] - nm0);
                S[mt][nt][2] = __expf(S[mt][nt][2] - nm1);
                S[mt][nt][3] = __expf(S[mt][nt][3] - nm1);
                rs0 += S[mt][nt][0] + S[mt][nt][1];
                rs1 += S[mt][nt][2] + S[mt][nt][3];
            }
            rs0 += __shfl_xor_sync(0xffffffffu, rs0, 1);
            rs0 += __shfl_xor_sync(0xffffffffu, rs0, 2);
            rs1 += __shfl_xor_sync(0xffffffffu, rs1, 1);
            rs1 += __shfl_xor_sync(0xffffffffu, rs1, 2);
            l0r[mt] = l0r[mt] * sc0 + rs0;
            l1r[mt] = l1r[mt] * sc1 + rs1;

#pragma unroll
            for (int nt = 0; nt < 8; nt++) {
                O[mt][nt][0] *= sc0; O[mt][nt][1] *= sc0;
                O[mt][nt][2] *= sc1; O[mt][nt][3] *= sc1;
            }

            // store P (warp-private rows), tf32-rounded
            {
                float* p0 = Pbuf + (wm + mt * 16 + rq) * FSTR + 2 * cq;
                float* p1 = p0 + 8 * FSTR;
#pragma unroll
                for (int nt = 0; nt < 8; nt++) {
                    *(float2*)(p0 + nt * 8) =
                        make_float2(tf32_round(S[mt][nt][0]), tf32_round(S[mt][nt][1]));
                    *(float2*)(p1 + nt * 8) =
                        make_float2(tf32_round(S[mt][nt][2]), tf32_round(S[mt][nt][3]));
                }
            }
        }
        __syncwarp();

        // ---- O += P V for both m-tiles (V frags shared) ----
        const uint32_t pb0 = sP + (uint32_t)(((wm + row_add) * FSTR + koff) * 4);
        const uint32_t pb1 = pb0 + (uint32_t)(16 * FSTR * 4);
        const uint32_t vb = sVt + (uint32_t)((kt & 1) * KV_TILE * 4)
                          + (uint32_t)((row_add * FSTR + koff) * 4);
#pragma unroll
        for (int ks = 0; ks < 8; ks++) {
            uint32_t aA0, aA1, aA2, aA3, aB0, aB1, aB2, aB3;
            {
                uint32_t r0, r1, r2, r3;
                ldsm_x4(r0, r1, r2, r3, pb0 + (uint32_t)(ks * 32));
                aA0 = r0; aA1 = r2; aA2 = r1; aA3 = r3;
                ldsm_x4(r0, r1, r2, r3, pb1 + (uint32_t)(ks * 32));
                aB0 = r0; aB1 = r2; aB2 = r1; aB3 = r3;
            }
#pragma unroll
            for (int p = 0; p < 4; p++) {
                uint32_t v0, v1, v2, v3;
                ldsm_x4(v0, v1, v2, v3, vb + (uint32_t)((p * 16 * FSTR) * 4 + ks * 32));
                const int n0 = 2 * p, n1 = 2 * p + 1;
                mma_tf32(O[0][n0][0], O[0][n0][1], O[0][n0][2], O[0][n0][3],
                         aA0, aA1, aA2, aA3, v0, v1);
                mma_tf32(O[0][n1][0], O[0][n1][1], O[0][n1][2], O[0][n1][3],
                         aA0, aA1, aA2, aA3, v2, v3);
                mma_tf32(O[1][n0][0], O[1][n0][1], O[1][n0][2], O[1][n0][3],
                         aB0, aB1, aB2, aB3, v0, v1);
                mma_tf32(O[1][n1][0], O[1][n1][1], O[1][n1][2], O[1][n1][3],
                         aB0, aB1, aB2, aB3, v2, v3);
            }
        }
    }

    // ---- epilogue per m-tile: attn fp32 + tf32-rounded fc input ----
#pragma unroll
    for (int mt = 0; mt < 2; mt++) {
        const float inv0 = 1.f / l0r[mt];
        const float inv1 = 1.f / l1r[mt];
        const size_t base_off =
            ((size_t)b * Ss + q0 + wm + mt * 16 + rq) * Dd + h * DP + 2 * cq;
        float* o0 = Out + base_off;
        float* o1 = o0 + (size_t)8 * Dd;
        float* f0 = FCin + base_off;
        float* f1 = f0 + (size_t)8 * Dd;
#pragma unroll
        for (int nt = 0; nt < 8; nt++) {
            float a = O[mt][nt][0] * inv0, bb2 = O[mt][nt][1] * inv0;
            float c = O[mt][nt][2] * inv1, d = O[mt][nt][3] * inv1;
            *(float2*)(o0 + nt * 8) = make_float2(a, bb2);
            *(float2*)(o1 + nt * 8) = make_float2(c, d);
            *(float2*)(f0 + nt * 8) = make_float2(tf32_round(a), tf32_round(bb2));
            *(float2*)(f1 + nt * 8) = make_float2(tf32_round(c), tf32_round(d));
        }
    }
}

// ---------------------------------------------------------------------------
extern "C" void kernel_launch(void* const* d_in, const int* in_sizes, int n_in,
                              void* d_out, int out_size)
{
    const float* q    = (const float*)d_in[0];
    const float* k    = (const float*)d_in[1];
    const float* v    = (const float*)d_in[2];
    const float* mask = (const float*)d_in[3];
    const float* wq_w = (const float*)d_in[4];
    const float* wq_b = (const float*)d_in[5];
    const float* wk_w = (const float*)d_in[6];
    const float* wk_b = (const float*)d_in[7];
    const float* wv_w = (const float*)d_in[8];
    const float* wv_b = (const float*)d_in[9];
    const float* fc_w = (const float*)d_in[10];
    const float* fc_b = (const float*)d_in[11];

    float *pQ, *pKh, *pVT, *pScr, *pFC;
    float *pqr, *pkr, *pvr, *pwqr, *pwkr, *pwvr, *pwfr;
    cudaGetSymbolAddress((void**)&pQ, g_Qp);
    cudaGetSymbolAddress((void**)&pKh, g_Kh);
    cudaGetSymbolAddress((void**)&pVT, g_VT);
    cudaGetSymbolAddress((void**)&pScr, g_attn_scratch);
    cudaGetSymbolAddress((void**)&pFC, g_FCin);
    cudaGetSymbolAddress((void**)&pqr, g_qr);
    cudaGetSymbolAddress((void**)&pkr, g_kr);
    cudaGetSymbolAddress((void**)&pvr, g_vr);
    cudaGetSymbolAddress((void**)&pwqr, g_wqr);
    cudaGetSymbolAddress((void**)&pwkr, g_wkr);
    cudaGetSymbolAddress((void**)&pwvr, g_wvr);
    cudaGetSymbolAddress((void**)&pwfr, g_wfr);

    float* out_main = (float*)d_out;
    const size_t OUT1 = (size_t)MM * Dd;
    float* attn_out = ((size_t)out_size >= 2 * OUT1) ? (out_main + OUT1) : pScr;

    static bool attr_set = false;
    if (!attr_set) {
        cudaFuncSetAttribute(flash_attn_tc, cudaFuncAttributeMaxDynamicSharedMemorySize,
                             FLASH_SMEM_BYTES);
        attr_set = true;
    }

    // Stage 0: tf32 rounding pre-pass (7 simple streaming launches)
    const int NA4 = (MM * Dd) / 4;       // 1M float4
    const int NW4 = (Dd * Dd) / 4;       // 256K float4
    round_tf32_kernel<<<(NA4 + 255) / 256, 256>>>((const float4*)q, (float4*)pqr, NA4);
    round_tf32_kernel<<<(NA4 + 255) / 256, 256>>>((const float4*)k, (float4*)pkr, NA4);
    round_tf32_kernel<<<(NA4 + 255) / 256, 256>>>((const float4*)v, (float4*)pvr, NA4);
    round_tf32_kernel<<<(NW4 + 255) / 256, 256>>>((const float4*)wq_w, (float4*)pwqr, NW4);
    round_tf32_kernel<<<(NW4 + 255) / 256, 256>>>((const float4*)wk_w, (float4*)pwkr, NW4);
    round_tf32_kernel<<<(NW4 + 255) / 256, 256>>>((const float4*)wv_w, (float4*)pwvr, NW4);
    round_tf32_kernel<<<(NW4 + 255) / 256, 256>>>((const float4*)fc_w, (float4*)pwfr, NW4);

    qkv_gemm<<<dim3(Dd / GBN, MM / GBM, 3), 256>>>(
        pqr, pkr, pvr, pwqr, pwkr, pwvr, wq_b, wk_b, wv_b, pQ, pKh, pVT);

    flash_attn_tc<<<dim3(Ss / 128, Hh, Bb), 128, FLASH_SMEM_BYTES>>>(
        pQ, pKh, pVT, mask, attn_out, pFC);

    fc_gemm<<<dim3(Dd / GBN, MM / GBM), 256>>>(pFC, pwfr, fc_b, out_main);
}